// round 2
// baseline (speedup 1.0000x reference)
#include <cuda_runtime.h>
#include <math.h>

// ---------------- problem constants ----------------
#define BB   64      // batch
#define TSR  64      // src len
#define TTR  64      // trg len
#define EE   512     // embedding
#define HH   512     // encoder hidden per dir
#define DDH  1024    // decoder hidden
#define VOC  32000
#define TD   63              // decode steps
#define MR   (TD*BB)         // 4032 rows of av
#define NT_V (VOC/64)        // 500 column tiles of vocab

// ---------------- static device scratch (~220 MB) ----------------
__device__ float g_sv   [BB*TSR*EE];        // src embedded, row = b*TSR+t
__device__ float g_tv   [MR*EE];            // trg embedded, row = t*BB+b
__device__ float g_Gf   [BB*TSR*4*HH];      // enc fwd preact (x@Wih^T + b)
__device__ float g_Gr   [BB*TSR*4*HH];
__device__ float g_Gdec [MR*4*DDH];         // dec preact (emb part) + dec_b
__device__ float g_Henc [BB*TSR*2*HH];      // [b*TSR+t][dir*512+j]
__device__ float g_Cenc [BB*TSR*2*HH];
__device__ float g_hs   [2*BB*HH];          // enc running h (both dirs)
__device__ float g_cs   [2*BB*HH];
__device__ float g_Penc [2*BB*4*HH];        // enc gate partials
__device__ float g_h    [BB*DDH];           // dec h
__device__ float g_c    [BB*DDH];           // dec c
__device__ float g_av   [BB*DDH];           // dec av (carry)
__device__ float g_ctx  [BB*DDH];           // attention context
__device__ float g_Pdec [4*BB*4*DDH];       // dec gate partials (4 K-slices)
__device__ float g_Phid [4*BB*DDH];         // hid/init partials (4 K-slices)
__device__ float g_final[BB*2*DDH];         // concat(Henc,Cenc) at last
__device__ float g_avall[MR*DDH];           // all av rows for vocab GEMM
__device__ float g_chunk[MR*NT_V*2];        // per-tile (max, sumexp)
__device__ float g_gold [MR];               // gold logits
__device__ int   g_goldtok[MR];
__device__ float g_maskf[MR];
__device__ float g_rowval[MR];              // (gold - lse) * mask

__device__ __forceinline__ float sigf(float x) { return 1.0f / (1.0f + expf(-x)); }

// ---------------- init / gathers ----------------
__global__ void k_zero_state() {
    int i = blockIdx.x * blockDim.x + threadIdx.x;
    if (i < 2 * BB * HH) { g_hs[i] = 0.f; g_cs[i] = 0.f; }
    if (i < BB * DDH)    { g_av[i] = 0.f; }
}

__global__ void k_gather_src(const int* __restrict__ tok, const float* __restrict__ emb) {
    int r = blockIdx.x;                 // b*TSR + t
    int v = tok[r];
    const float4* s = (const float4*)(emb + (long)v * EE);
    float4* d = (float4*)(g_sv + (long)r * EE);
    d[threadIdx.x] = s[threadIdx.x];    // 128 threads * 4 = 512
}

__global__ void k_gather_trg(const int* __restrict__ tok, const int* __restrict__ lens,
                             const float* __restrict__ emb) {
    int r = blockIdx.x;                 // t*BB + b, t in [0,63)
    int t = r >> 6, b = r & 63;
    int v = tok[b * TTR + t];
    const float4* s = (const float4*)(emb + (long)v * EE);
    float4* d = (float4*)(g_tv + (long)r * EE);
    d[threadIdx.x] = s[threadIdx.x];
    if (threadIdx.x == 0) {
        g_goldtok[r] = tok[b * TTR + t + 1];
        g_maskf[r] = ((t + 1) < lens[b]) ? 1.0f : 0.0f;
    }
}

// ---------------- generic 64x64 GEMM: C = A @ W^T + bias ----------------
// grid.x = M/64 (fastest), grid.y = N/64; 128 threads
__global__ void k_gemm_bias(const float* __restrict__ A, int lda,
                            const float* __restrict__ W, int ldw,
                            const float* __restrict__ bias,
                            float* __restrict__ C, int ldc, int K) {
    __shared__ float As[16][64];
    __shared__ float Ws[16][64];
    int tid = threadIdx.x;
    int m0 = blockIdx.x * 64, n0 = blockIdx.y * 64;
    int ty = tid >> 3, tx = tid & 7;
    int lr = tid >> 1, lc = (tid & 1) * 8;
    float acc[4][8];
#pragma unroll
    for (int i = 0; i < 4; i++)
#pragma unroll
        for (int j = 0; j < 8; j++) acc[i][j] = 0.f;
    const float* Ab = A + (long)(m0 + lr) * lda + lc;
    const float* Wb = W + (long)(n0 + lr) * ldw + lc;
    for (int k0 = 0; k0 < K; k0 += 16) {
        float4 a0 = *(const float4*)(Ab + k0);
        float4 a1 = *(const float4*)(Ab + k0 + 4);
        float4 b0 = *(const float4*)(Wb + k0);
        float4 b1 = *(const float4*)(Wb + k0 + 4);
        __syncthreads();
        As[lc + 0][lr] = a0.x; As[lc + 1][lr] = a0.y; As[lc + 2][lr] = a0.z; As[lc + 3][lr] = a0.w;
        As[lc + 4][lr] = a1.x; As[lc + 5][lr] = a1.y; As[lc + 6][lr] = a1.z; As[lc + 7][lr] = a1.w;
        Ws[lc + 0][lr] = b0.x; Ws[lc + 1][lr] = b0.y; Ws[lc + 2][lr] = b0.z; Ws[lc + 3][lr] = b0.w;
        Ws[lc + 4][lr] = b1.x; Ws[lc + 5][lr] = b1.y; Ws[lc + 6][lr] = b1.z; Ws[lc + 7][lr] = b1.w;
        __syncthreads();
#pragma unroll
        for (int kk = 0; kk < 16; kk++) {
            float a[4], b[8];
#pragma unroll
            for (int i = 0; i < 4; i++) a[i] = As[kk][ty * 4 + i];
#pragma unroll
            for (int j = 0; j < 8; j++) b[j] = Ws[kk][tx * 8 + j];
#pragma unroll
            for (int i = 0; i < 4; i++)
#pragma unroll
                for (int j = 0; j < 8; j++) acc[i][j] += a[i] * b[j];
        }
    }
#pragma unroll
    for (int i = 0; i < 4; i++) {
        long row = m0 + ty * 4 + i;
#pragma unroll
        for (int j = 0; j < 8; j++)
            C[row * (long)ldc + n0 + tx * 8 + j] = acc[i][j] + bias[n0 + tx * 8 + j];
    }
}

// ---------------- vocab GEMM + fused LSE chunk epilogue ----------------
// A = g_avall [4032,1024], W = out_W [32000,1024]; grid(63, 500), 128 thr
__global__ void k_gemm_lse(const float* __restrict__ A,
                           const float* __restrict__ W,
                           const float* __restrict__ bias) {
    __shared__ float As[16][64];
    __shared__ float Ws[16][64];
    __shared__ float Cs[64][65];
    int tid = threadIdx.x;
    int m0 = blockIdx.x * 64, n0 = blockIdx.y * 64;
    int ty = tid >> 3, tx = tid & 7;
    int lr = tid >> 1, lc = (tid & 1) * 8;
    float acc[4][8];
#pragma unroll
    for (int i = 0; i < 4; i++)
#pragma unroll
        for (int j = 0; j < 8; j++) acc[i][j] = 0.f;
    const float* Ab = A + (long)(m0 + lr) * DDH + lc;
    const float* Wb = W + (long)(n0 + lr) * DDH + lc;
    for (int k0 = 0; k0 < DDH; k0 += 16) {
        float4 a0 = *(const float4*)(Ab + k0);
        float4 a1 = *(const float4*)(Ab + k0 + 4);
        float4 b0 = *(const float4*)(Wb + k0);
        float4 b1 = *(const float4*)(Wb + k0 + 4);
        __syncthreads();
        As[lc + 0][lr] = a0.x; As[lc + 1][lr] = a0.y; As[lc + 2][lr] = a0.z; As[lc + 3][lr] = a0.w;
        As[lc + 4][lr] = a1.x; As[lc + 5][lr] = a1.y; As[lc + 6][lr] = a1.z; As[lc + 7][lr] = a1.w;
        Ws[lc + 0][lr] = b0.x; Ws[lc + 1][lr] = b0.y; Ws[lc + 2][lr] = b0.z; Ws[lc + 3][lr] = b0.w;
        Ws[lc + 4][lr] = b1.x; Ws[lc + 5][lr] = b1.y; Ws[lc + 6][lr] = b1.z; Ws[lc + 7][lr] = b1.w;
        __syncthreads();
#pragma unroll
        for (int kk = 0; kk < 16; kk++) {
            float a[4], b[8];
#pragma unroll
            for (int i = 0; i < 4; i++) a[i] = As[kk][ty * 4 + i];
#pragma unroll
            for (int j = 0; j < 8; j++) b[j] = Ws[kk][tx * 8 + j];
#pragma unroll
            for (int i = 0; i < 4; i++)
#pragma unroll
                for (int j = 0; j < 8; j++) acc[i][j] += a[i] * b[j];
        }
    }
#pragma unroll
    for (int i = 0; i < 4; i++)
#pragma unroll
        for (int j = 0; j < 8; j++)
            Cs[ty * 4 + i][tx * 8 + j] = acc[i][j] + bias[n0 + tx * 8 + j];
    __syncthreads();
    if (tid < 64) {
        int rg = m0 + tid;
        float m = -1e30f;
#pragma unroll 8
        for (int c = 0; c < 64; c++) m = fmaxf(m, Cs[tid][c]);
        float s = 0.f;
#pragma unroll 8
        for (int c = 0; c < 64; c++) s += __expf(Cs[tid][c] - m);
        long co = ((long)rg * NT_V + blockIdx.y) * 2;
        g_chunk[co + 0] = m;
        g_chunk[co + 1] = s;
        int loc = g_goldtok[rg] - n0;
        if (loc >= 0 && loc < 64) g_gold[rg] = Cs[tid][loc];
    }
}

// ---------------- skinny GEMM: M=64, BN=32, split-K (512-chunks) ----------------
// z < c0 -> source0 chunk z; else source1 chunk (z-c0). P[z][64][N]
__global__ void k_sgemm(const float* __restrict__ A0, int lda0,
                        const float* __restrict__ W0, int ldw0, int c0,
                        const float* __restrict__ A1, int lda1,
                        const float* __restrict__ W1, int ldw1,
                        float* __restrict__ P, int N) {
    __shared__ float As[16][64];
    __shared__ float Ws[16][32];
    int z = blockIdx.z;
    const float* A; const float* W; int lda, ldw, koff;
    if (z < c0) { A = A0; W = W0; lda = lda0; ldw = ldw0; koff = z * 512; }
    else        { A = A1; W = W1; lda = lda1; ldw = ldw1; koff = (z - c0) * 512; }
    int tid = threadIdx.x;
    int n0 = blockIdx.x * 32;
    int ty = tid >> 3, tx = tid & 7;
    int lr = tid >> 1, lc = (tid & 1) * 8;
    int wr = tid >> 2, wc = (tid & 3) * 4;
    float acc[4][4];
#pragma unroll
    for (int i = 0; i < 4; i++)
#pragma unroll
        for (int j = 0; j < 4; j++) acc[i][j] = 0.f;
    const float* Ab = A + (long)lr * lda + koff + lc;
    const float* Wb = W + (long)(n0 + wr) * ldw + koff + wc;
    for (int k0 = 0; k0 < 512; k0 += 16) {
        float4 a0 = *(const float4*)(Ab + k0);
        float4 a1 = *(const float4*)(Ab + k0 + 4);
        float4 b0 = *(const float4*)(Wb + k0);
        __syncthreads();
        As[lc + 0][lr] = a0.x; As[lc + 1][lr] = a0.y; As[lc + 2][lr] = a0.z; As[lc + 3][lr] = a0.w;
        As[lc + 4][lr] = a1.x; As[lc + 5][lr] = a1.y; As[lc + 6][lr] = a1.z; As[lc + 7][lr] = a1.w;
        Ws[wc + 0][wr] = b0.x; Ws[wc + 1][wr] = b0.y; Ws[wc + 2][wr] = b0.z; Ws[wc + 3][wr] = b0.w;
        __syncthreads();
#pragma unroll
        for (int kk = 0; kk < 16; kk++) {
            float a[4], b[4];
#pragma unroll
            for (int i = 0; i < 4; i++) a[i] = As[kk][ty * 4 + i];
#pragma unroll
            for (int j = 0; j < 4; j++) b[j] = Ws[kk][tx * 4 + j];
#pragma unroll
            for (int i = 0; i < 4; i++)
#pragma unroll
                for (int j = 0; j < 4; j++) acc[i][j] += a[i] * b[j];
        }
    }
    float* Pz = P + (long)z * 64 * N;
#pragma unroll
    for (int i = 0; i < 4; i++)
#pragma unroll
        for (int j = 0; j < 4; j++)
            Pz[(ty * 4 + i) * (long)N + n0 + tx * 4 + j] = acc[i][j];
}

// ---------------- encoder recurrent-gates GEMM (both dirs) ----------------
// grid(64, 2), 128 thr: P_enc[d] = h_state[d] @ Whh_d^T   (N=2048, K=512)
__global__ void k_enc_gates(const float* __restrict__ Wf, const float* __restrict__ Wr) {
    __shared__ float As[16][64];
    __shared__ float Ws[16][32];
    int d = blockIdx.y;
    const float* A = g_hs + d * (BB * HH);
    const float* W = d ? Wr : Wf;
    int tid = threadIdx.x;
    int n0 = blockIdx.x * 32;
    int ty = tid >> 3, tx = tid & 7;
    int lr = tid >> 1, lc = (tid & 1) * 8;
    int wr = tid >> 2, wc = (tid & 3) * 4;
    float acc[4][4];
#pragma unroll
    for (int i = 0; i < 4; i++)
#pragma unroll
        for (int j = 0; j < 4; j++) acc[i][j] = 0.f;
    const float* Ab = A + (long)lr * HH + lc;
    const float* Wb = W + (long)(n0 + wr) * HH + wc;
    for (int k0 = 0; k0 < 512; k0 += 16) {
        float4 a0 = *(const float4*)(Ab + k0);
        float4 a1 = *(const float4*)(Ab + k0 + 4);
        float4 b0 = *(const float4*)(Wb + k0);
        __syncthreads();
        As[lc + 0][lr] = a0.x; As[lc + 1][lr] = a0.y; As[lc + 2][lr] = a0.z; As[lc + 3][lr] = a0.w;
        As[lc + 4][lr] = a1.x; As[lc + 5][lr] = a1.y; As[lc + 6][lr] = a1.z; As[lc + 7][lr] = a1.w;
        Ws[wc + 0][wr] = b0.x; Ws[wc + 1][wr] = b0.y; Ws[wc + 2][wr] = b0.z; Ws[wc + 3][wr] = b0.w;
        __syncthreads();
#pragma unroll
        for (int kk = 0; kk < 16; kk++) {
            float a[4], b[4];
#pragma unroll
            for (int i = 0; i < 4; i++) a[i] = As[kk][ty * 4 + i];
#pragma unroll
            for (int j = 0; j < 4; j++) b[j] = Ws[kk][tx * 4 + j];
#pragma unroll
            for (int i = 0; i < 4; i++)
#pragma unroll
                for (int j = 0; j < 4; j++) acc[i][j] += a[i] * b[j];
        }
    }
    float* Pz = g_Penc + (long)d * (BB * 4 * HH);
#pragma unroll
    for (int i = 0; i < 4; i++)
#pragma unroll
        for (int j = 0; j < 4; j++)
            Pz[(ty * 4 + i) * (4 * HH) + n0 + tx * 4 + j] = acc[i][j];
}

// ---------------- encoder cell update ----------------
__global__ void k_enc_cell(int t) {
    int i = blockIdx.x * blockDim.x + threadIdx.x;    // < 2*64*512
    int d = i >> 15;
    int r = i & 32767;
    int b = r >> 9, j = r & 511;
    const float* pre = (d ? g_Gr : g_Gf) + (long)(b * TSR + t) * (4 * HH);
    const float* Pd = g_Penc + (long)d * (BB * 4 * HH) + (long)b * (4 * HH);
    float gi = Pd[j]        + pre[j];
    float gf = Pd[j + 512]  + pre[j + 512];
    float gg = Pd[j + 1024] + pre[j + 1024];
    float go = Pd[j + 1536] + pre[j + 1536];
    int si = d * BB * HH + b * HH + j;
    float c = sigf(gf) * g_cs[si] + sigf(gi) * tanhf(gg);
    float h = sigf(go) * tanhf(c);
    g_cs[si] = c; g_hs[si] = h;
    long o = (long)(b * TSR + t) * (2 * HH) + d * HH + j;
    g_Henc[o] = h; g_Cenc[o] = c;
}

// ---------------- decoder init ----------------
__global__ void k_final(const int* __restrict__ src_lens) {
    int i = blockIdx.x * blockDim.x + threadIdx.x;    // < 64*2048
    int b = i >> 11, j = i & 2047;
    int last = src_lens[b] - 1;
    long o = (long)(b * TSR + last) * (2 * HH);
    g_final[i] = (j < 1024) ? g_Henc[o + j] : g_Cenc[o + j - 1024];
}

__global__ void k_init(const float* __restrict__ init_b) {
    int i = blockIdx.x * blockDim.x + threadIdx.x;    // < 64*1024
    int j = i & 1023;
    float c = init_b[j];
#pragma unroll
    for (int s = 0; s < 4; s++) c += g_Phid[s * (BB * DDH) + i];
    g_c[i] = c;
    g_h[i] = tanhf(c);
}

// ---------------- decoder cell ----------------
__global__ void k_dec_cell(int t) {
    int i = blockIdx.x * blockDim.x + threadIdx.x;    // < 64*1024
    int b = i >> 10, j = i & 1023;
    const float* pre = g_Gdec + (long)(t * BB + b) * (4 * DDH);
    float gi = pre[j], gf = pre[j + 1024], gg = pre[j + 2048], go = pre[j + 3072];
#pragma unroll
    for (int s = 0; s < 4; s++) {
        const float* Ps = g_Pdec + (long)s * (BB * 4 * DDH) + (long)b * (4 * DDH);
        gi += Ps[j]; gf += Ps[j + 1024]; gg += Ps[j + 2048]; go += Ps[j + 3072];
    }
    float c = sigf(gf) * g_c[i] + sigf(gi) * tanhf(gg);
    float h = sigf(go) * tanhf(c);
    g_c[i] = c; g_h[i] = h;
}

// ---------------- attention (one block per batch row) ----------------
__global__ void k_attn(const int* __restrict__ src_lens) {
    __shared__ float sh[1024];
    __shared__ float sc[64];
    __shared__ float sp[64];
    int b = blockIdx.x, tid = threadIdx.x;
    float4* shv = (float4*)sh;
    const float4* hv = (const float4*)(g_h + (long)b * DDH);
    shv[tid] = hv[tid]; shv[tid + 128] = hv[tid + 128];
    __syncthreads();
    int tt = tid >> 1, half = tid & 1;
    {
        const float* He = g_Henc + (long)(b * TSR + tt) * DDH + half * 512;
        const float* hh = sh + half * 512;
        float s = 0.f;
#pragma unroll 8
        for (int j = 0; j < 512; j++) s += hh[j] * He[j];
        s += __shfl_xor_sync(0xffffffffu, s, 1);
        if (!half) sc[tt] = s;
    }
    __syncthreads();
    int L = src_lens[b];
    float m = -1e30f;
    for (int u = 0; u < 64; u++) if (u < L) m = fmaxf(m, sc[u]);
    float den = 0.f;
    for (int u = 0; u < 64; u++) if (u < L) den += __expf(sc[u] - m);
    if (tid < 64) sp[tid] = (tid < L) ? (__expf(sc[tid] - m) / den) : 0.f;
    __syncthreads();
    int j0 = tid * 8;
    float acc[8];
#pragma unroll
    for (int k = 0; k < 8; k++) acc[k] = 0.f;
    for (int u = 0; u < L; u++) {
        float p = sp[u];
        const float4* Hr = (const float4*)(g_Henc + (long)(b * TSR + u) * DDH + j0);
        float4 v0 = Hr[0], v1 = Hr[1];
        acc[0] += p * v0.x; acc[1] += p * v0.y; acc[2] += p * v0.z; acc[3] += p * v0.w;
        acc[4] += p * v1.x; acc[5] += p * v1.y; acc[6] += p * v1.z; acc[7] += p * v1.w;
    }
    float* co = g_ctx + (long)b * DDH + j0;
#pragma unroll
    for (int k = 0; k < 8; k++) co[k] = acc[k];
}

// ---------------- av combine ----------------
__global__ void k_av(const float* __restrict__ hid_b, int t) {
    int i = blockIdx.x * blockDim.x + threadIdx.x;    // < 64*1024
    int b = i >> 10, j = i & 1023;
    float v = hid_b[j];
#pragma unroll
    for (int s = 0; s < 4; s++) v += g_Phid[s * (BB * DDH) + i];
    g_av[i] = v;
    g_avall[(long)(t * BB + b) * DDH + j] = v;
}

// ---------------- per-row LSE combine ----------------
__global__ void k_rowlse() {
    int tid = threadIdx.x;                 // 256
    int b = tid >> 2, q = tid & 3;
    int row = blockIdx.x * 64 + b;
    const float* ch = g_chunk + (long)row * NT_V * 2;
    float m = -1e30f;
    for (int i = q; i < NT_V; i += 4) m = fmaxf(m, ch[2 * i]);
    m = fmaxf(m, __shfl_xor_sync(0xffffffffu, m, 1));
    m = fmaxf(m, __shfl_xor_sync(0xffffffffu, m, 2));
    float s = 0.f;
    for (int i = q; i < NT_V; i += 4) s += ch[2 * i + 1] * __expf(ch[2 * i] - m);
    s += __shfl_xor_sync(0xffffffffu, s, 1);
    s += __shfl_xor_sync(0xffffffffu, s, 2);
    if (q == 0) {
        float lse = m + logf(s);
        g_rowval[row] = (g_gold[row] - lse) * g_maskf[row];
    }
}

__global__ void k_sum(float* __restrict__ out) {
    __shared__ float sm[256];
    int tid = threadIdx.x;
    float s = 0.f;
    for (int i = tid; i < MR; i += 256) s += g_rowval[i];
    sm[tid] = s;
    __syncthreads();
    for (int st = 128; st > 0; st >>= 1) {
        if (tid < st) sm[tid] += sm[tid + st];
        __syncthreads();
    }
    if (tid == 0) out[0] = sm[0];
}

// ---------------- launch ----------------
extern "C" void kernel_launch(void* const* d_in, const int* in_sizes, int n_in,
                              void* d_out, int out_size) {
    (void)in_sizes; (void)n_in; (void)out_size;
    const int*   src_tokens = (const int*)d_in[0];
    const int*   src_lens   = (const int*)d_in[1];
    const int*   trg_tokens = (const int*)d_in[2];
    const int*   trg_lens   = (const int*)d_in[3];
    const float* src_emb    = (const float*)d_in[4];
    const float* trg_emb    = (const float*)d_in[5];
    const float* enc_Wih    = (const float*)d_in[6];
    const float* enc_Whh    = (const float*)d_in[7];
    const float* enc_b      = (const float*)d_in[8];
    const float* rev_Wih    = (const float*)d_in[9];
    const float* rev_Whh    = (const float*)d_in[10];
    const float* rev_b      = (const float*)d_in[11];
    const float* dec_Wih    = (const float*)d_in[12];
    const float* dec_Whh    = (const float*)d_in[13];
    const float* dec_b      = (const float*)d_in[14];
    const float* hid_W      = (const float*)d_in[15];
    const float* hid_b      = (const float*)d_in[16];
    const float* out_W      = (const float*)d_in[17];
    const float* out_b      = (const float*)d_in[18];
    const float* init_W     = (const float*)d_in[19];
    const float* init_b     = (const float*)d_in[20];

    float *p_sv, *p_tv, *p_Gf, *p_Gr, *p_Gdec, *p_h, *p_av, *p_ctx, *p_final,
          *p_Pdec, *p_Phid, *p_avall;
    cudaGetSymbolAddress((void**)&p_sv, g_sv);
    cudaGetSymbolAddress((void**)&p_tv, g_tv);
    cudaGetSymbolAddress((void**)&p_Gf, g_Gf);
    cudaGetSymbolAddress((void**)&p_Gr, g_Gr);
    cudaGetSymbolAddress((void**)&p_Gdec, g_Gdec);
    cudaGetSymbolAddress((void**)&p_h, g_h);
    cudaGetSymbolAddress((void**)&p_av, g_av);
    cudaGetSymbolAddress((void**)&p_ctx, g_ctx);
    cudaGetSymbolAddress((void**)&p_final, g_final);
    cudaGetSymbolAddress((void**)&p_Pdec, g_Pdec);
    cudaGetSymbolAddress((void**)&p_Phid, g_Phid);
    cudaGetSymbolAddress((void**)&p_avall, g_avall);

    k_zero_state<<<256, 256>>>();
    k_gather_src<<<BB * TSR, 128>>>(src_tokens, src_emb);
    k_gather_trg<<<MR, 128>>>(trg_tokens, trg_lens, trg_emb);

    // input projections
    k_gemm_bias<<<dim3(64, 32), 128>>>(p_sv, EE, enc_Wih, EE, enc_b, p_Gf, 4 * HH, EE);
    k_gemm_bias<<<dim3(64, 32), 128>>>(p_sv, EE, rev_Wih, EE, rev_b, p_Gr, 4 * HH, EE);
    k_gemm_bias<<<dim3(63, 64), 128>>>(p_tv, EE, dec_Wih, EE + DDH, dec_b, p_Gdec, 4 * DDH, EE);

    // encoder recurrence (both dirs forward scan)
    for (int t = 0; t < TSR; t++) {
        k_enc_gates<<<dim3(64, 2), 128>>>(enc_Whh, rev_Whh);
        k_enc_cell<<<256, 256>>>(t);
    }

    // decoder init state
    k_final<<<512, 256>>>(src_lens);
    k_sgemm<<<dim3(32, 1, 4), 128>>>(p_final, 2 * DDH, init_W, 2 * DDH, 4,
                                     (const float*)0, 0, (const float*)0, 0, p_Phid, DDH);
    k_init<<<256, 256>>>(init_b);

    // decoder recurrence
    for (int t = 0; t < TD; t++) {
        k_sgemm<<<dim3(128, 1, 4), 128>>>(p_av, DDH, dec_Wih + EE, EE + DDH, 2,
                                          p_h, DDH, dec_Whh, DDH, p_Pdec, 4 * DDH);
        k_dec_cell<<<256, 256>>>(t);
        k_attn<<<BB, 128>>>(src_lens);
        k_sgemm<<<dim3(32, 1, 4), 128>>>(p_h, DDH, hid_W, 2 * DDH, 2,
                                         p_ctx, DDH, hid_W + DDH, 2 * DDH, p_Phid, DDH);
        k_av<<<256, 256>>>(hid_b, t);
    }

    // vocab projection with fused LSE chunks
    k_gemm_lse<<<dim3(63, NT_V), 128>>>(p_avall, out_W, out_b);
    k_rowlse<<<63, 256>>>();
    k_sum<<<1, 256>>>((float*)d_out);
}

// round 3
// speedup vs baseline: 1.8396x; 1.8396x over previous
#include <cuda_runtime.h>
#include <cuda_bf16.h>
#include <mma.h>
#include <math.h>
using namespace nvcuda;

// ---------------- problem constants ----------------
#define BB   64      // batch
#define TSR  64      // src len
#define TTR  64      // trg len
#define EE   512     // embedding
#define HH   512     // encoder hidden per dir
#define DDH  1024    // decoder hidden
#define VOC  32000
#define TD   63              // decode steps
#define MR   (TD*BB)         // 4032 rows of av
#define NT_V (VOC/64)        // 500 column tiles of vocab

// ---------------- static device scratch ----------------
__device__ __nv_bfloat16 g_svb  [BB*TSR*EE];     // src embedded bf16, row = b*TSR+t
__device__ __nv_bfloat16 g_tvb  [MR*EE];         // trg embedded bf16, row = t*BB+b
__device__ __nv_bfloat16 g_Wencf[4*HH*EE];       // enc_Wih bf16
__device__ __nv_bfloat16 g_Wencr[4*HH*EE];       // rev_Wih bf16
__device__ __nv_bfloat16 g_Wdec [4*DDH*(EE+DDH)];// dec_Wih bf16 (full, ld=1536)
__device__ __nv_bfloat16 g_Wout [VOC*DDH];       // out_W bf16
__device__ __nv_bfloat16 g_avallb[MR*DDH];       // all av rows bf16 for vocab GEMM

__device__ float g_Gf   [BB*TSR*4*HH];      // enc fwd preact (x@Wih^T + b)
__device__ float g_Gr   [BB*TSR*4*HH];
__device__ float g_Gdec [MR*4*DDH];         // dec preact (emb part) + dec_b
__device__ float g_Henc [BB*TSR*2*HH];      // [b*TSR+t][dir*512+j]
__device__ float g_Cenc [BB*TSR*2*HH];
__device__ float g_hs   [2*BB*HH];          // enc running h (both dirs)
__device__ float g_cs   [2*BB*HH];
__device__ float g_Penc [2*BB*4*HH];        // enc gate partials
__device__ float g_h    [BB*DDH];           // dec h
__device__ float g_c    [BB*DDH];           // dec c
__device__ float g_av   [BB*DDH];           // dec av (carry, fp32 for recurrent GEMM)
__device__ float g_ctx  [BB*DDH];           // attention context
__device__ float g_Pdec [4*BB*4*DDH];       // dec gate partials (4 K-slices)
__device__ float g_Phid [4*BB*DDH];         // hid/init partials (4 K-slices)
__device__ float g_final[BB*2*DDH];         // concat(Henc,Cenc) at last
__device__ float g_chunk[MR*NT_V*2];        // per-tile (max, sumexp)
__device__ float g_gold [MR];               // gold logits
__device__ int   g_goldtok[MR];
__device__ float g_maskf[MR];
__device__ float g_rowval[MR];              // (gold - lse) * mask

__device__ __forceinline__ float sigf(float x) { return 1.0f / (1.0f + expf(-x)); }

// ---------------- fp32 -> bf16 converter (4-wide) ----------------
__global__ void k_f2b(const float* __restrict__ x, __nv_bfloat16* __restrict__ y, int n4) {
    int i = blockIdx.x * blockDim.x + threadIdx.x;
    if (i < n4) {
        float4 v = ((const float4*)x)[i];
        __nv_bfloat162 a = __float22bfloat162_rn(make_float2(v.x, v.y));
        __nv_bfloat162 b = __float22bfloat162_rn(make_float2(v.z, v.w));
        ((__nv_bfloat162*)y)[2 * i]     = a;
        ((__nv_bfloat162*)y)[2 * i + 1] = b;
    }
}

// ---------------- init / gathers ----------------
__global__ void k_zero_state() {
    int i = blockIdx.x * blockDim.x + threadIdx.x;
    if (i < 2 * BB * HH) { g_hs[i] = 0.f; g_cs[i] = 0.f; }
    if (i < BB * DDH)    { g_av[i] = 0.f; }
}

__global__ void k_gather_src(const int* __restrict__ tok, const float* __restrict__ emb) {
    int r = blockIdx.x;                 // b*TSR + t
    int v = tok[r];
    const float4* s = (const float4*)(emb + (long)v * EE);
    float4 val = s[threadIdx.x];        // 128 threads * 4 = 512
    __nv_bfloat162 a = __float22bfloat162_rn(make_float2(val.x, val.y));
    __nv_bfloat162 b = __float22bfloat162_rn(make_float2(val.z, val.w));
    __nv_bfloat162* d = (__nv_bfloat162*)(g_svb + (long)r * EE + threadIdx.x * 4);
    d[0] = a; d[1] = b;
}

__global__ void k_gather_trg(const int* __restrict__ tok, const int* __restrict__ lens,
                             const float* __restrict__ emb) {
    int r = blockIdx.x;                 // t*BB + b, t in [0,63)
    int t = r >> 6, b = r & 63;
    int v = tok[b * TTR + t];
    const float4* s = (const float4*)(emb + (long)v * EE);
    float4 val = s[threadIdx.x];
    __nv_bfloat162 a = __float22bfloat162_rn(make_float2(val.x, val.y));
    __nv_bfloat162 b2 = __float22bfloat162_rn(make_float2(val.z, val.w));
    __nv_bfloat162* d = (__nv_bfloat162*)(g_tvb + (long)r * EE + threadIdx.x * 4);
    d[0] = a; d[1] = b2;
    if (threadIdx.x == 0) {
        g_goldtok[r] = tok[b * TTR + t + 1];
        g_maskf[r] = ((t + 1) < lens[b]) ? 1.0f : 0.0f;
    }
}

// ---------------- bf16 tensor-core GEMM: C = A @ W^T + bias ----------------
// A bf16 [M, lda], W bf16 [N, ldw] (row-major; we use W^T), K multiple of 32.
// 64x64 tile, 128 threads = 4 warps, each warp a 32x32 quadrant.
// LSE==1: instead of writing C, compute per-64-col-chunk (max, sumexp) + gold capture.
template <int LSE>
__global__ void k_wgemm(const __nv_bfloat16* __restrict__ A, int lda,
                        const __nv_bfloat16* __restrict__ W, int ldw,
                        const float* __restrict__ bias,
                        float* __restrict__ C, int ldc, int K) {
    __shared__ __align__(32) __nv_bfloat16 As[64][40];
    __shared__ __align__(32) __nv_bfloat16 Ws[64][40];
    __shared__ float Cs[64][72];
    int tid = threadIdx.x;
    int wid = tid >> 5;
    int m0 = blockIdx.x * 64, n0 = blockIdx.y * 64;
    int wr = (wid >> 1) * 32, wc = (wid & 1) * 32;

    wmma::fragment<wmma::accumulator, 16, 16, 16, float> acc[2][2];
#pragma unroll
    for (int i = 0; i < 2; i++)
#pragma unroll
        for (int j = 0; j < 2; j++) wmma::fill_fragment(acc[i][j], 0.f);

    int lr = tid >> 2;            // 0..31
    int lc = (tid & 3) * 8;       // 0,8,16,24
    const __nv_bfloat16* Ab0 = A + (long)(m0 + lr) * lda + lc;
    const __nv_bfloat16* Ab1 = A + (long)(m0 + lr + 32) * lda + lc;
    const __nv_bfloat16* Wb0 = W + (long)(n0 + lr) * ldw + lc;
    const __nv_bfloat16* Wb1 = W + (long)(n0 + lr + 32) * ldw + lc;

    for (int k0 = 0; k0 < K; k0 += 32) {
        __syncthreads();
        *(float4*)(&As[lr][lc])      = *(const float4*)(Ab0 + k0);
        *(float4*)(&As[lr + 32][lc]) = *(const float4*)(Ab1 + k0);
        *(float4*)(&Ws[lr][lc])      = *(const float4*)(Wb0 + k0);
        *(float4*)(&Ws[lr + 32][lc]) = *(const float4*)(Wb1 + k0);
        __syncthreads();
#pragma unroll
        for (int kk = 0; kk < 32; kk += 16) {
            wmma::fragment<wmma::matrix_a, 16, 16, 16, __nv_bfloat16, wmma::row_major> af[2];
            wmma::fragment<wmma::matrix_b, 16, 16, 16, __nv_bfloat16, wmma::col_major> bf[2];
            wmma::load_matrix_sync(af[0], &As[wr][kk], 40);
            wmma::load_matrix_sync(af[1], &As[wr + 16][kk], 40);
            wmma::load_matrix_sync(bf[0], &Ws[wc][kk], 40);
            wmma::load_matrix_sync(bf[1], &Ws[wc + 16][kk], 40);
#pragma unroll
            for (int i = 0; i < 2; i++)
#pragma unroll
                for (int j = 0; j < 2; j++)
                    wmma::mma_sync(acc[i][j], af[i], bf[j], acc[i][j]);
        }
    }
#pragma unroll
    for (int i = 0; i < 2; i++)
#pragma unroll
        for (int j = 0; j < 2; j++)
            wmma::store_matrix_sync(&Cs[wr + i * 16][wc + j * 16], acc[i][j], 72,
                                    wmma::mem_row_major);
    __syncthreads();

    if (LSE) {
        // add bias into Cs
#pragma unroll
        for (int e = tid; e < 64 * 64; e += 128) {
            int r = e >> 6, cc = e & 63;
            Cs[r][cc] += bias[n0 + cc];
        }
        __syncthreads();
        int row = tid >> 1, half = (tid & 1) * 32;
        float m = -1e30f;
#pragma unroll 8
        for (int cc = 0; cc < 32; cc++) m = fmaxf(m, Cs[row][half + cc]);
        m = fmaxf(m, __shfl_xor_sync(0xffffffffu, m, 1));
        float s = 0.f;
#pragma unroll 8
        for (int cc = 0; cc < 32; cc++) s += __expf(Cs[row][half + cc] - m);
        s += __shfl_xor_sync(0xffffffffu, s, 1);
        if ((tid & 1) == 0) {
            int rg = m0 + row;
            long co = ((long)rg * NT_V + blockIdx.y) * 2;
            g_chunk[co + 0] = m;
            g_chunk[co + 1] = s;
            int loc = g_goldtok[rg] - n0;
            if (loc >= 0 && loc < 64) g_gold[rg] = Cs[row][loc];
        }
    } else {
#pragma unroll
        for (int e = tid; e < 64 * 64; e += 128) {
            int r = e >> 6, cc = e & 63;
            C[(long)(m0 + r) * ldc + n0 + cc] = Cs[r][cc] + bias[n0 + cc];
        }
    }
}

// ---------------- skinny fp32 GEMM: M=64, BN=32, split-K (512-chunks) ----------------
__global__ void k_sgemm(const float* __restrict__ A0, int lda0,
                        const float* __restrict__ W0, int ldw0, int c0,
                        const float* __restrict__ A1, int lda1,
                        const float* __restrict__ W1, int ldw1,
                        float* __restrict__ P, int N) {
    __shared__ float As[16][64];
    __shared__ float Ws[16][32];
    int z = blockIdx.z;
    const float* A; const float* W; int lda, ldw, koff;
    if (z < c0) { A = A0; W = W0; lda = lda0; ldw = ldw0; koff = z * 512; }
    else        { A = A1; W = W1; lda = lda1; ldw = ldw1; koff = (z - c0) * 512; }
    int tid = threadIdx.x;
    int n0 = blockIdx.x * 32;
    int ty = tid >> 3, tx = tid & 7;
    int lr = tid >> 1, lc = (tid & 1) * 8;
    int wr = tid >> 2, wc = (tid & 3) * 4;
    float acc[4][4];
#pragma unroll
    for (int i = 0; i < 4; i++)
#pragma unroll
        for (int j = 0; j < 4; j++) acc[i][j] = 0.f;
    const float* Ab = A + (long)lr * lda + koff + lc;
    const float* Wb = W + (long)(n0 + wr) * ldw + koff + wc;
    for (int k0 = 0; k0 < 512; k0 += 16) {
        float4 a0 = *(const float4*)(Ab + k0);
        float4 a1 = *(const float4*)(Ab + k0 + 4);
        float4 b0 = *(const float4*)(Wb + k0);
        __syncthreads();
        As[lc + 0][lr] = a0.x; As[lc + 1][lr] = a0.y; As[lc + 2][lr] = a0.z; As[lc + 3][lr] = a0.w;
        As[lc + 4][lr] = a1.x; As[lc + 5][lr] = a1.y; As[lc + 6][lr] = a1.z; As[lc + 7][lr] = a1.w;
        Ws[wc + 0][wr] = b0.x; Ws[wc + 1][wr] = b0.y; Ws[wc + 2][wr] = b0.z; Ws[wc + 3][wr] = b0.w;
        __syncthreads();
#pragma unroll
        for (int kk = 0; kk < 16; kk++) {
            float a[4], b[4];
#pragma unroll
            for (int i = 0; i < 4; i++) a[i] = As[kk][ty * 4 + i];
#pragma unroll
            for (int j = 0; j < 4; j++) b[j] = Ws[kk][tx * 4 + j];
#pragma unroll
            for (int i = 0; i < 4; i++)
#pragma unroll
                for (int j = 0; j < 4; j++) acc[i][j] += a[i] * b[j];
        }
    }
    float* Pz = P + (long)z * 64 * N;
#pragma unroll
    for (int i = 0; i < 4; i++)
#pragma unroll
        for (int j = 0; j < 4; j++)
            Pz[(ty * 4 + i) * (long)N + n0 + tx * 4 + j] = acc[i][j];
}

// ---------------- encoder recurrent-gates GEMM (both dirs) ----------------
__global__ void k_enc_gates(const float* __restrict__ Wf, const float* __restrict__ Wr) {
    __shared__ float As[16][64];
    __shared__ float Ws[16][32];
    int d = blockIdx.y;
    const float* A = g_hs + d * (BB * HH);
    const float* W = d ? Wr : Wf;
    int tid = threadIdx.x;
    int n0 = blockIdx.x * 32;
    int ty = tid >> 3, tx = tid & 7;
    int lr = tid >> 1, lc = (tid & 1) * 8;
    int wr = tid >> 2, wc = (tid & 3) * 4;
    float acc[4][4];
#pragma unroll
    for (int i = 0; i < 4; i++)
#pragma unroll
        for (int j = 0; j < 4; j++) acc[i][j] = 0.f;
    const float* Ab = A + (long)lr * HH + lc;
    const float* Wb = W + (long)(n0 + wr) * HH + wc;
    for (int k0 = 0; k0 < 512; k0 += 16) {
        float4 a0 = *(const float4*)(Ab + k0);
        float4 a1 = *(const float4*)(Ab + k0 + 4);
        float4 b0 = *(const float4*)(Wb + k0);
        __syncthreads();
        As[lc + 0][lr] = a0.x; As[lc + 1][lr] = a0.y; As[lc + 2][lr] = a0.z; As[lc + 3][lr] = a0.w;
        As[lc + 4][lr] = a1.x; As[lc + 5][lr] = a1.y; As[lc + 6][lr] = a1.z; As[lc + 7][lr] = a1.w;
        Ws[wc + 0][wr] = b0.x; Ws[wc + 1][wr] = b0.y; Ws[wc + 2][wr] = b0.z; Ws[wc + 3][wr] = b0.w;
        __syncthreads();
#pragma unroll
        for (int kk = 0; kk < 16; kk++) {
            float a[4], b[4];
#pragma unroll
            for (int i = 0; i < 4; i++) a[i] = As[kk][ty * 4 + i];
#pragma unroll
            for (int j = 0; j < 4; j++) b[j] = Ws[kk][tx * 4 + j];
#pragma unroll
            for (int i = 0; i < 4; i++)
#pragma unroll
                for (int j = 0; j < 4; j++) acc[i][j] += a[i] * b[j];
        }
    }
    float* Pz = g_Penc + (long)d * (BB * 4 * HH);
#pragma unroll
    for (int i = 0; i < 4; i++)
#pragma unroll
        for (int j = 0; j < 4; j++)
            Pz[(ty * 4 + i) * (4 * HH) + n0 + tx * 4 + j] = acc[i][j];
}

// ---------------- encoder cell update ----------------
__global__ void k_enc_cell(int t) {
    int i = blockIdx.x * blockDim.x + threadIdx.x;    // < 2*64*512
    int d = i >> 15;
    int r = i & 32767;
    int b = r >> 9, j = r & 511;
    const float* pre = (d ? g_Gr : g_Gf) + (long)(b * TSR + t) * (4 * HH);
    const float* Pd = g_Penc + (long)d * (BB * 4 * HH) + (long)b * (4 * HH);
    float gi = Pd[j]        + pre[j];
    float gf = Pd[j + 512]  + pre[j + 512];
    float gg = Pd[j + 1024] + pre[j + 1024];
    float go = Pd[j + 1536] + pre[j + 1536];
    int si = d * BB * HH + b * HH + j;
    float c = sigf(gf) * g_cs[si] + sigf(gi) * tanhf(gg);
    float h = sigf(go) * tanhf(c);
    g_cs[si] = c; g_hs[si] = h;
    long o = (long)(b * TSR + t) * (2 * HH) + d * HH + j;
    g_Henc[o] = h; g_Cenc[o] = c;
}

// ---------------- decoder init ----------------
__global__ void k_final(const int* __restrict__ src_lens) {
    int i = blockIdx.x * blockDim.x + threadIdx.x;    // < 64*2048
    int b = i >> 11, j = i & 2047;
    int last = src_lens[b] - 1;
    long o = (long)(b * TSR + last) * (2 * HH);
    g_final[i] = (j < 1024) ? g_Henc[o + j] : g_Cenc[o + j - 1024];
}

__global__ void k_init(const float* __restrict__ init_b) {
    int i = blockIdx.x * blockDim.x + threadIdx.x;    // < 64*1024
    int j = i & 1023;
    float c = init_b[j];
#pragma unroll
    for (int s = 0; s < 4; s++) c += g_Phid[s * (BB * DDH) + i];
    g_c[i] = c;
    g_h[i] = tanhf(c);
}

// ---------------- fused decoder cell + attention (one block per batch row) ----------------
__global__ void k_dec_cell_attn(int t, const int* __restrict__ src_lens) {
    __shared__ float sh[1024];
    __shared__ float sc[64];
    __shared__ float sp[64];
    int b = blockIdx.x, tid = threadIdx.x;   // 256 threads
    // LSTM cell for this batch row (4 elems per thread)
    const float* pre = g_Gdec + (long)(t * BB + b) * (4 * DDH);
#pragma unroll
    for (int u = 0; u < 4; u++) {
        int j = tid + u * 256;
        float gi = pre[j], gf = pre[j + 1024], gg = pre[j + 2048], go = pre[j + 3072];
#pragma unroll
        for (int s = 0; s < 4; s++) {
            const float* Ps = g_Pdec + (long)s * (BB * 4 * DDH) + (long)b * (4 * DDH);
            gi += Ps[j]; gf += Ps[j + 1024]; gg += Ps[j + 2048]; go += Ps[j + 3072];
        }
        int ci = b * DDH + j;
        float c = sigf(gf) * g_c[ci] + sigf(gi) * tanhf(gg);
        float h = sigf(go) * tanhf(c);
        g_c[ci] = c; g_h[ci] = h; sh[j] = h;
    }
    __syncthreads();
    // scores: 4 threads per src position
    {
        int tt = tid >> 2, q = tid & 3;
        const float* He = g_Henc + (long)(b * TSR + tt) * DDH + q * 256;
        const float* hh = sh + q * 256;
        float s = 0.f;
#pragma unroll 8
        for (int j = 0; j < 256; j++) s += hh[j] * He[j];
        s += __shfl_xor_sync(0xffffffffu, s, 1);
        s += __shfl_xor_sync(0xffffffffu, s, 2);
        if (q == 0) sc[tt] = s;
    }
    __syncthreads();
    int L = src_lens[b];
    float m = -1e30f;
    for (int u = 0; u < 64; u++) if (u < L) m = fmaxf(m, sc[u]);
    float den = 0.f;
    for (int u = 0; u < 64; u++) if (u < L) den += __expf(sc[u] - m);
    if (tid < 64) sp[tid] = (tid < L) ? (__expf(sc[tid] - m) / den) : 0.f;
    __syncthreads();
    // context: 4 outputs per thread
    int j0 = tid * 4;
    float a0 = 0.f, a1 = 0.f, a2 = 0.f, a3 = 0.f;
    for (int u = 0; u < L; u++) {
        float p = sp[u];
        float4 v = *(const float4*)(g_Henc + (long)(b * TSR + u) * DDH + j0);
        a0 += p * v.x; a1 += p * v.y; a2 += p * v.z; a3 += p * v.w;
    }
    float4 o; o.x = a0; o.y = a1; o.z = a2; o.w = a3;
    *(float4*)(g_ctx + (long)b * DDH + j0) = o;
}

// ---------------- av combine ----------------
__global__ void k_av(const float* __restrict__ hid_b, int t) {
    int i = blockIdx.x * blockDim.x + threadIdx.x;    // < 64*1024
    int b = i >> 10, j = i & 1023;
    float v = hid_b[j];
#pragma unroll
    for (int s = 0; s < 4; s++) v += g_Phid[s * (BB * DDH) + i];
    g_av[i] = v;
    g_avallb[(long)(t * BB + b) * DDH + j] = __float2bfloat16(v);
}

// ---------------- per-row LSE combine ----------------
__global__ void k_rowlse() {
    int tid = threadIdx.x;                 // 256
    int b = tid >> 2, q = tid & 3;
    int row = blockIdx.x * 64 + b;
    const float* ch = g_chunk + (long)row * NT_V * 2;
    float m = -1e30f;
    for (int i = q; i < NT_V; i += 4) m = fmaxf(m, ch[2 * i]);
    m = fmaxf(m, __shfl_xor_sync(0xffffffffu, m, 1));
    m = fmaxf(m, __shfl_xor_sync(0xffffffffu, m, 2));
    float s = 0.f;
    for (int i = q; i < NT_V; i += 4) s += ch[2 * i + 1] * __expf(ch[2 * i] - m);
    s += __shfl_xor_sync(0xffffffffu, s, 1);
    s += __shfl_xor_sync(0xffffffffu, s, 2);
    if (q == 0) {
        float lse = m + logf(s);
        g_rowval[row] = (g_gold[row] - lse) * g_maskf[row];
    }
}

__global__ void k_sum(float* __restrict__ out) {
    __shared__ float sm[256];
    int tid = threadIdx.x;
    float s = 0.f;
    for (int i = tid; i < MR; i += 256) s += g_rowval[i];
    sm[tid] = s;
    __syncthreads();
    for (int st = 128; st > 0; st >>= 1) {
        if (tid < st) sm[tid] += sm[tid + st];
        __syncthreads();
    }
    if (tid == 0) out[0] = sm[0];
}

// ---------------- launch ----------------
extern "C" void kernel_launch(void* const* d_in, const int* in_sizes, int n_in,
                              void* d_out, int out_size) {
    (void)in_sizes; (void)n_in; (void)out_size;
    const int*   src_tokens = (const int*)d_in[0];
    const int*   src_lens   = (const int*)d_in[1];
    const int*   trg_tokens = (const int*)d_in[2];
    const int*   trg_lens   = (const int*)d_in[3];
    const float* src_emb    = (const float*)d_in[4];
    const float* trg_emb    = (const float*)d_in[5];
    const float* enc_Wih    = (const float*)d_in[6];
    const float* enc_Whh    = (const float*)d_in[7];
    const float* enc_b      = (const float*)d_in[8];
    const float* rev_Wih    = (const float*)d_in[9];
    const float* rev_Whh    = (const float*)d_in[10];
    const float* rev_b      = (const float*)d_in[11];
    const float* dec_Wih    = (const float*)d_in[12];
    const float* dec_Whh    = (const float*)d_in[13];
    const float* dec_b      = (const float*)d_in[14];
    const float* hid_W      = (const float*)d_in[15];
    const float* hid_b      = (const float*)d_in[16];
    const float* out_W      = (const float*)d_in[17];
    const float* out_b      = (const float*)d_in[18];
    const float* init_W     = (const float*)d_in[19];
    const float* init_b     = (const float*)d_in[20];

    float *p_Gf, *p_Gr, *p_Gdec, *p_h, *p_av, *p_ctx, *p_final, *p_Pdec, *p_Phid;
    __nv_bfloat16 *p_svb, *p_tvb, *p_Wencf, *p_Wencr, *p_Wdec, *p_Wout, *p_avallb;
    cudaGetSymbolAddress((void**)&p_Gf, g_Gf);
    cudaGetSymbolAddress((void**)&p_Gr, g_Gr);
    cudaGetSymbolAddress((void**)&p_Gdec, g_Gdec);
    cudaGetSymbolAddress((void**)&p_h, g_h);
    cudaGetSymbolAddress((void**)&p_av, g_av);
    cudaGetSymbolAddress((void**)&p_ctx, g_ctx);
    cudaGetSymbolAddress((void**)&p_final, g_final);
    cudaGetSymbolAddress((void**)&p_Pdec, g_Pdec);
    cudaGetSymbolAddress((void**)&p_Phid, g_Phid);
    cudaGetSymbolAddress((void**)&p_svb, g_svb);
    cudaGetSymbolAddress((void**)&p_tvb, g_tvb);
    cudaGetSymbolAddress((void**)&p_Wencf, g_Wencf);
    cudaGetSymbolAddress((void**)&p_Wencr, g_Wencr);
    cudaGetSymbolAddress((void**)&p_Wdec, g_Wdec);
    cudaGetSymbolAddress((void**)&p_Wout, g_Wout);
    cudaGetSymbolAddress((void**)&p_avallb, g_avallb);

    k_zero_state<<<256, 256>>>();
    k_gather_src<<<BB * TSR, 128>>>(src_tokens, src_emb);
    k_gather_trg<<<MR, 128>>>(trg_tokens, trg_lens, trg_emb);

    // weight conversions to bf16
    k_f2b<<<(4 * HH * EE / 4 + 255) / 256, 256>>>(enc_Wih, p_Wencf, 4 * HH * EE / 4);
    k_f2b<<<(4 * HH * EE / 4 + 255) / 256, 256>>>(rev_Wih, p_Wencr, 4 * HH * EE / 4);
    k_f2b<<<(4 * DDH * (EE + DDH) / 4 + 255) / 256, 256>>>(dec_Wih, p_Wdec, 4 * DDH * (EE + DDH) / 4);
    k_f2b<<<(VOC * DDH / 4 + 255) / 256, 256>>>(out_W, p_Wout, VOC * DDH / 4);

    // input projections (tensor cores)
    k_wgemm<0><<<dim3(64, 32), 128>>>(p_svb, EE, p_Wencf, EE, enc_b, p_Gf, 4 * HH, EE);
    k_wgemm<0><<<dim3(64, 32), 128>>>(p_svb, EE, p_Wencr, EE, rev_b, p_Gr, 4 * HH, EE);
    k_wgemm<0><<<dim3(63, 64), 128>>>(p_tvb, EE, p_Wdec, EE + DDH, dec_b, p_Gdec, 4 * DDH, EE);

    // encoder recurrence (both dirs forward scan, fp32)
    for (int t = 0; t < TSR; t++) {
        k_enc_gates<<<dim3(64, 2), 128>>>(enc_Whh, rev_Whh);
        k_enc_cell<<<256, 256>>>(t);
    }

    // decoder init state
    k_final<<<512, 256>>>(src_lens);
    k_sgemm<<<dim3(32, 1, 4), 128>>>(p_final, 2 * DDH, init_W, 2 * DDH, 4,
                                     (const float*)0, 0, (const float*)0, 0, p_Phid, DDH);
    k_init<<<256, 256>>>(init_b);

    // decoder recurrence (fp32 GEMMs, fused cell+attention)
    for (int t = 0; t < TD; t++) {
        k_sgemm<<<dim3(128, 1, 4), 128>>>(p_av, DDH, dec_Wih + EE, EE + DDH, 2,
                                          p_h, DDH, dec_Whh, DDH, p_Pdec, 4 * DDH);
        k_dec_cell_attn<<<BB, 256>>>(t, src_lens);
        k_sgemm<<<dim3(32, 1, 4), 128>>>(p_h, DDH, hid_W, 2 * DDH, 2,
                                         p_ctx, DDH, hid_W + DDH, 2 * DDH, p_Phid, DDH);
        k_av<<<256, 256>>>(hid_b, t);
    }

    // vocab projection with fused LSE chunks (tensor cores)
    k_wgemm<1><<<dim3(63, NT_V), 128>>>(p_avallb, DDH, p_Wout, DDH, out_b,
                                        (float*)0, 0, DDH);
    k_rowlse<<<63, 256>>>();
    k_sum<<<1, 256>>>((float*)d_out);
}

// round 4
// speedup vs baseline: 2.0911x; 1.1367x over previous
#include <cuda_runtime.h>
#include <cuda_bf16.h>
#include <mma.h>
#include <math.h>
using namespace nvcuda;

// ---------------- problem constants ----------------
#define BB   64      // batch
#define TSR  64      // src len
#define TTR  64      // trg len
#define EE   512     // embedding
#define HH   512     // encoder hidden per dir
#define DDH  1024    // decoder hidden
#define VOC  32000
#define TD   63              // decode steps
#define MR   (TD*BB)         // 4032 rows of av
#define NTV  (VOC/128)       // 250 column tiles of vocab

typedef __nv_bfloat16 bf16;
typedef __nv_bfloat162 bf162;

// ---------------- static device scratch ----------------
__device__ bf16 g_svb  [BB*TSR*EE];       // src embedded bf16, row = b*TSR+t
__device__ bf16 g_tvb  [MR*EE];           // trg embedded bf16, row = t*BB+b
__device__ bf16 g_WencfP[4*HH*EE];        // enc_Wih bf16, gate-interleaved rows
__device__ bf16 g_WencrP[4*HH*EE];
__device__ bf16 g_WhhfP [4*HH*HH];        // enc_Whh bf16 interleaved
__device__ bf16 g_WhhrP [4*HH*HH];
__device__ bf16 g_WdecE [4*DDH*EE];       // dec_Wih[:, :512] interleaved
__device__ bf16 g_WdecR [4*DDH*2048];     // [dec_Wih[:,512:1536] | dec_Whh] interleaved
__device__ bf16 g_WhidB [DDH*2*DDH];      // hid_W bf16 plain
__device__ bf16 g_Wout  [VOC*DDH];        // out_W bf16 plain
__device__ bf16 g_avallb[MR*DDH];         // all av rows bf16

__device__ float g_bencfP[4*HH];          // permuted biases (fp32)
__device__ float g_bencrP[4*HH];
__device__ float g_bdecP [4*DDH];

__device__ float g_Gf   [BB*TSR*4*HH];    // enc fwd preact (interleaved cols)
__device__ float g_Gr   [BB*TSR*4*HH];
__device__ float g_Gdec [MR*4*DDH];       // dec preact (emb part + bias, interleaved)
__device__ float g_Henc [BB*TSR*2*HH];    // fp32 (for final-state gather)
__device__ float g_Cenc [BB*TSR*2*HH];
__device__ bf16  g_Hencb[BB*TSR*2*HH];    // bf16 copy for attention
__device__ bf16  g_hsb  [2*BB*HH];        // enc running h bf16 (both dirs)
__device__ float g_cs   [2*BB*HH];        // enc running c fp32
__device__ float g_h    [BB*DDH];         // dec h fp32 (attention)
__device__ float g_c    [BB*DDH];         // dec c fp32
__device__ bf16  g_xb   [BB*2048];        // [av | h] bf16: gates GEMM input
__device__ bf16  g_yb   [BB*2048];        // [h | ctx] bf16: hid GEMM input
__device__ float g_Phid [4*BB*DDH];       // init-GEMM split-K partials
__device__ float g_final[BB*2*DDH];       // concat(Henc,Cenc) at last
__device__ float g_chunk[MR*NTV*2];       // per-tile (max, sumexp)
__device__ float g_gold [MR];
__device__ int   g_goldtok[MR];
__device__ float g_maskf[MR];
__device__ float g_rowval[MR];

__device__ __forceinline__ float sigf(float x) { return 1.0f / (1.0f + expf(-x)); }
__device__ __forceinline__ bf162 cvt2(float a, float b) {
    return __float22bfloat162_rn(make_float2(a, b));
}

// ============ shared 64x128 GEMM core (bf16, fp32 accum) ============
// 256 threads / 8 warps. Double-buffered smem, one sync per K-iter.
// Result left in Cs[64][136] (smem, aliased with the staging buffers).
__device__ __forceinline__ void gemm_core(
    const bf16* __restrict__ A, int lda,
    const bf16* __restrict__ W, int ldw,   // W tile base: 128 rows
    int K, float* Cs)
{
    bf16* As = (bf16*)Cs;            // 2 * 64 * 40 bf16
    bf16* Ws = (bf16*)Cs + 5120;     // 2 * 128 * 40 bf16
    int tid = threadIdx.x;
    int wid = tid >> 5;
    int wr = (wid & 1) * 32, wc = (wid >> 1) * 32;

    wmma::fragment<wmma::accumulator, 16, 16, 16, float> acc[2][2];
#pragma unroll
    for (int i = 0; i < 2; i++)
#pragma unroll
        for (int j = 0; j < 2; j++) wmma::fill_fragment(acc[i][j], 0.f);

    int lr = tid >> 2, lc = (tid & 3) * 8;
    const bf16* Ap  = A + (size_t)lr * lda + lc;
    const bf16* Wp0 = W + (size_t)lr * ldw + lc;
    const bf16* Wp1 = W + (size_t)(lr + 64) * ldw + lc;

    float4 ra  = *(const float4*)Ap;
    float4 rw0 = *(const float4*)Wp0;
    float4 rw1 = *(const float4*)Wp1;
    *(float4*)&As[lr * 40 + lc] = ra;
    *(float4*)&Ws[lr * 40 + lc] = rw0;
    *(float4*)&Ws[(lr + 64) * 40 + lc] = rw1;

    int niter = K >> 5;
    int cur = 0;
    for (int it = 0; it < niter; ++it) {
        __syncthreads();
        if (it + 1 < niter) {
            ra  = *(const float4*)(Ap  + (it + 1) * 32);
            rw0 = *(const float4*)(Wp0 + (it + 1) * 32);
            rw1 = *(const float4*)(Wp1 + (it + 1) * 32);
        }
        const bf16* Ab = As + cur * (64 * 40);
        const bf16* Wb = Ws + cur * (128 * 40);
#pragma unroll
        for (int kk = 0; kk < 32; kk += 16) {
            wmma::fragment<wmma::matrix_a, 16, 16, 16, bf16, wmma::row_major> af[2];
            wmma::fragment<wmma::matrix_b, 16, 16, 16, bf16, wmma::col_major> bfr[2];
            wmma::load_matrix_sync(af[0], Ab + wr * 40 + kk, 40);
            wmma::load_matrix_sync(af[1], Ab + (wr + 16) * 40 + kk, 40);
            wmma::load_matrix_sync(bfr[0], Wb + wc * 40 + kk, 40);
            wmma::load_matrix_sync(bfr[1], Wb + (wc + 16) * 40 + kk, 40);
#pragma unroll
            for (int i = 0; i < 2; i++)
#pragma unroll
                for (int j = 0; j < 2; j++)
                    wmma::mma_sync(acc[i][j], af[i], bfr[j], acc[i][j]);
        }
        if (it + 1 < niter) {
            int nb = cur ^ 1;
            *(float4*)&As[(nb * 64 + lr) * 40 + lc] = ra;
            *(float4*)&Ws[(nb * 128 + lr) * 40 + lc] = rw0;
            *(float4*)&Ws[(nb * 128 + lr + 64) * 40 + lc] = rw1;
        }
        cur ^= 1;
    }
    __syncthreads();
#pragma unroll
    for (int i = 0; i < 2; i++)
#pragma unroll
        for (int j = 0; j < 2; j++)
            wmma::store_matrix_sync(Cs + (wr + i * 16) * 136 + wc + j * 16,
                                    acc[i][j], 136, wmma::mem_row_major);
    __syncthreads();
}

// ---------------- conversions / permutations ----------------
__global__ void k_f2b(const float* __restrict__ x, bf16* __restrict__ y, int n4) {
    int i = blockIdx.x * blockDim.x + threadIdx.x;
    if (i < n4) {
        float4 v = ((const float4*)x)[i];
        ((bf162*)y)[2 * i]     = cvt2(v.x, v.y);
        ((bf162*)y)[2 * i + 1] = cvt2(v.z, v.w);
    }
}

// out row (4j+g) <- W row (g*J+j), first 512 cols of ldin
__global__ void k_permW512(const float* __restrict__ W, bf16* __restrict__ out,
                           int J, int ldin) {
    int row = blockIdx.x;
    int j = row >> 2, g = row & 3;
    const float4* src = (const float4*)(W + (size_t)(g * J + j) * ldin);
    bf162* dst = (bf162*)(out + (size_t)row * 512);
    int t = threadIdx.x;                   // 128
    float4 v = src[t];
    dst[2 * t]     = cvt2(v.x, v.y);
    dst[2 * t + 1] = cvt2(v.z, v.w);
}

__global__ void k_permDecR(const float* __restrict__ Wih, const float* __restrict__ Whh) {
    int row = blockIdx.x;                  // 4096
    int j = row >> 2, g = row & 3;
    int t = threadIdx.x;                   // 256, 8 elems each
    const float* src = (t < 128)
        ? (Wih + (size_t)(g * 1024 + j) * 1536 + 512 + t * 8)
        : (Whh + (size_t)(g * 1024 + j) * 1024 + (t - 128) * 8);
    bf162* dst = (bf162*)(g_WdecR + (size_t)row * 2048 + t * 8);
    float4 a = *(const float4*)src;
    float4 b = *(const float4*)(src + 4);
    dst[0] = cvt2(a.x, a.y); dst[1] = cvt2(a.z, a.w);
    dst[2] = cvt2(b.x, b.y); dst[3] = cvt2(b.z, b.w);
}

__global__ void k_permB(const float* __restrict__ b, float* __restrict__ out, int J) {
    int i = blockIdx.x * blockDim.x + threadIdx.x;
    if (i < 4 * J) { int j = i >> 2, g = i & 3; out[i] = b[g * J + j]; }
}

// ---------------- init / gathers ----------------
__global__ void k_zero_state() {
    int i = blockIdx.x * blockDim.x + threadIdx.x;
    if (i < 2 * BB * HH) { g_cs[i] = 0.f; g_hsb[i] = __float2bfloat16(0.f); }
}

__global__ void k_gather_src(const int* __restrict__ tok, const float* __restrict__ emb) {
    int r = blockIdx.x;
    int v = tok[r];
    float4 val = ((const float4*)(emb + (size_t)v * EE))[threadIdx.x];
    bf162* d = (bf162*)(g_svb + (size_t)r * EE + threadIdx.x * 4);
    d[0] = cvt2(val.x, val.y); d[1] = cvt2(val.z, val.w);
}

__global__ void k_gather_trg(const int* __restrict__ tok, const int* __restrict__ lens,
                             const float* __restrict__ emb) {
    int r = blockIdx.x;                    // t*BB + b
    int t = r >> 6, b = r & 63;
    int v = tok[b * TTR + t];
    float4 val = ((const float4*)(emb + (size_t)v * EE))[threadIdx.x];
    bf162* d = (bf162*)(g_tvb + (size_t)r * EE + threadIdx.x * 4);
    d[0] = cvt2(val.x, val.y); d[1] = cvt2(val.z, val.w);
    if (threadIdx.x == 0) {
        g_goldtok[r] = tok[b * TTR + t + 1];
        g_maskf[r] = ((t + 1) < lens[b]) ? 1.0f : 0.0f;
    }
}

// ---------------- feed-forward GEMM: C = A @ W^T + bias ----------------
__global__ __launch_bounds__(256) void k_ff(
    const bf16* __restrict__ A, int lda,
    const bf16* __restrict__ W, int ldw,
    const float* __restrict__ bias,
    float* __restrict__ C, int ldc, int K)
{
    __shared__ __align__(16) float Cs[64 * 136];
    int m0 = blockIdx.x * 64, n0 = blockIdx.y * 128;
    gemm_core(A + (size_t)m0 * lda, lda, W + (size_t)n0 * ldw, ldw, K, Cs);
    int tid = threadIdx.x;
    for (int e = tid; e < 2048; e += 256) {
        int r = e >> 5, c4 = (e & 31) * 4;
        float4 v = *(const float4*)(Cs + r * 136 + c4);
        float4 bv = *(const float4*)(bias + n0 + c4);
        v.x += bv.x; v.y += bv.y; v.z += bv.z; v.w += bv.w;
        *(float4*)(C + (size_t)(m0 + r) * ldc + n0 + c4) = v;
    }
}

// ---------------- vocab GEMM + fused LSE chunk ----------------
__global__ __launch_bounds__(256) void k_vocab(const float* __restrict__ bias) {
    __shared__ __align__(16) float Cs[64 * 136];
    int m0 = blockIdx.x * 64, n0 = blockIdx.y * 128;
    gemm_core(g_avallb + (size_t)m0 * DDH, DDH, g_Wout + (size_t)n0 * DDH, DDH, DDH, Cs);
    int tid = threadIdx.x;
    // add bias
    for (int e = tid; e < 2048; e += 256) {
        int r = e >> 5, c4 = (e & 31) * 4;
        float4 v = *(const float4*)(Cs + r * 136 + c4);
        float4 bv = *(const float4*)(bias + n0 + c4);
        v.x += bv.x; v.y += bv.y; v.z += bv.z; v.w += bv.w;
        *(float4*)(Cs + r * 136 + c4) = v;
    }
    __syncthreads();
    int row = tid >> 2, q = tid & 3;
    const float* Cr = Cs + row * 136 + q * 32;
    float m = -1e30f;
#pragma unroll 8
    for (int c = 0; c < 32; c++) m = fmaxf(m, Cr[c]);
    m = fmaxf(m, __shfl_xor_sync(0xffffffffu, m, 1));
    m = fmaxf(m, __shfl_xor_sync(0xffffffffu, m, 2));
    float s = 0.f;
#pragma unroll 8
    for (int c = 0; c < 32; c++) s += __expf(Cr[c] - m);
    s += __shfl_xor_sync(0xffffffffu, s, 1);
    s += __shfl_xor_sync(0xffffffffu, s, 2);
    int rg = m0 + row;
    if (q == 0) {
        size_t co = ((size_t)rg * NTV + blockIdx.y) * 2;
        g_chunk[co + 0] = m;
        g_chunk[co + 1] = s;
    }
    int loc = g_goldtok[rg] - n0;
    if (loc >= q * 32 && loc < q * 32 + 32) g_gold[rg] = Cs[row * 136 + loc];
}

// ---------------- encoder step: recurrent gates GEMM + fused cell ----------------
__global__ __launch_bounds__(256) void k_enc_step(
    int t, const bf16* __restrict__ Wf, const bf16* __restrict__ Wr)
{
    __shared__ __align__(16) float Cs[64 * 136];
    int d = blockIdx.y;
    int n0 = blockIdx.x * 128;             // of 2048 interleaved cols
    const bf16* A = g_hsb + d * (BB * HH);
    const bf16* W = (d ? Wr : Wf) + (size_t)n0 * HH;
    gemm_core(A, HH, W, HH, HH, Cs);
    int tid = threadIdx.x;
    const float* pre_base = (d ? g_Gr : g_Gf);
    for (int it = tid; it < 2048; it += 256) {
        int b = it >> 5, jl = it & 31;
        const float* cr = Cs + b * 136 + 4 * jl;
        const float* pre = pre_base + (size_t)(b * TSR + t) * 2048 + n0 + 4 * jl;
        float gi = cr[0] + pre[0];
        float gf = cr[1] + pre[1];
        float gg = cr[2] + pre[2];
        float go = cr[3] + pre[3];
        int j = (n0 >> 2) + jl;
        int si = d * (BB * HH) + (b << 9) + j;
        float c = sigf(gf) * g_cs[si] + sigf(gi) * tanhf(gg);
        float h = sigf(go) * tanhf(c);
        g_cs[si] = c;
        g_hsb[si] = __float2bfloat16(h);
        size_t o = (size_t)(b * TSR + t) * 1024 + d * 512 + j;
        g_Henc[o] = h; g_Cenc[o] = c; g_Hencb[o] = __float2bfloat16(h);
    }
}

// ---------------- decoder step: gates GEMM + fused cell ----------------
__global__ __launch_bounds__(256) void k_dec_step(int t) {
    __shared__ __align__(16) float Cs[64 * 136];
    int n0 = blockIdx.x * 128;             // of 4096 interleaved cols
    gemm_core(g_xb, 2048, g_WdecR + (size_t)n0 * 2048, 2048, 2048, Cs);
    int tid = threadIdx.x;
    for (int it = tid; it < 2048; it += 256) {
        int b = it >> 5, jl = it & 31;
        const float* cr = Cs + b * 136 + 4 * jl;
        const float* pre = g_Gdec + (size_t)((t << 6) + b) * 4096 + n0 + 4 * jl;
        float gi = cr[0] + pre[0];
        float gf = cr[1] + pre[1];
        float gg = cr[2] + pre[2];
        float go = cr[3] + pre[3];
        int j = (n0 >> 2) + jl;
        int ci = (b << 10) + j;
        float c = sigf(gf) * g_c[ci] + sigf(gi) * tanhf(gg);
        float h = sigf(go) * tanhf(c);
        g_c[ci] = c; g_h[ci] = h;
        bf16 hb = __float2bfloat16(h);
        g_xb[b * 2048 + 1024 + j] = hb;    // for next step's gates GEMM
        g_yb[b * 2048 + j] = hb;           // for hid GEMM
    }
}

// ---------------- hid GEMM: av = [h|ctx] @ hid_W^T + hid_b ----------------
__global__ __launch_bounds__(256) void k_hid(const float* __restrict__ bias, int t) {
    __shared__ __align__(16) float Cs[64 * 136];
    int n0 = blockIdx.x * 128;             // of 1024
    gemm_core(g_yb, 2048, g_WhidB + (size_t)n0 * 2048, 2048, 2048, Cs);
    int tid = threadIdx.x;
    for (int e = tid; e < 8192; e += 256) {
        int r = e >> 7, c = e & 127;
        float v = Cs[r * 136 + c] + bias[n0 + c];
        int jn = n0 + c;
        bf16 vb = __float2bfloat16(v);
        g_xb[r * 2048 + jn] = vb;                          // av for next gates GEMM
        g_avallb[(size_t)((t << 6) + r) * 1024 + jn] = vb; // vocab GEMM row
    }
}

// ---------------- decoder init (fp32 path, one-time) ----------------
__global__ void k_final(const int* __restrict__ src_lens) {
    int i = blockIdx.x * blockDim.x + threadIdx.x;    // < 64*2048
    int b = i >> 11, j = i & 2047;
    int last = src_lens[b] - 1;
    size_t o = (size_t)(b * TSR + last) * 1024;
    g_final[i] = (j < 1024) ? g_Henc[o + j] : g_Cenc[o + j - 1024];
}

__global__ void k_sgemm_init(const float* __restrict__ W) {
    __shared__ float As[16][64];
    __shared__ float Ws[16][32];
    int z = blockIdx.z;
    int koff = z * 512;
    int tid = threadIdx.x;
    int n0 = blockIdx.x * 32;
    int ty = tid >> 3, tx = tid & 7;
    int lr = tid >> 1, lc = (tid & 1) * 8;
    int wr = tid >> 2, wc = (tid & 3) * 4;
    float acc[4][4];
#pragma unroll
    for (int i = 0; i < 4; i++)
#pragma unroll
        for (int j = 0; j < 4; j++) acc[i][j] = 0.f;
    const float* Ab = g_final + (size_t)lr * 2048 + koff + lc;
    const float* Wb = W + (size_t)(n0 + wr) * 2048 + koff + wc;
    for (int k0 = 0; k0 < 512; k0 += 16) {
        float4 a0 = *(const float4*)(Ab + k0);
        float4 a1 = *(const float4*)(Ab + k0 + 4);
        float4 b0 = *(const float4*)(Wb + k0);
        __syncthreads();
        As[lc + 0][lr] = a0.x; As[lc + 1][lr] = a0.y; As[lc + 2][lr] = a0.z; As[lc + 3][lr] = a0.w;
        As[lc + 4][lr] = a1.x; As[lc + 5][lr] = a1.y; As[lc + 6][lr] = a1.z; As[lc + 7][lr] = a1.w;
        Ws[wc + 0][wr] = b0.x; Ws[wc + 1][wr] = b0.y; Ws[wc + 2][wr] = b0.z; Ws[wc + 3][wr] = b0.w;
        __syncthreads();
#pragma unroll
        for (int kk = 0; kk < 16; kk++) {
            float a[4], b[4];
#pragma unroll
            for (int i = 0; i < 4; i++) a[i] = As[kk][ty * 4 + i];
#pragma unroll
            for (int j = 0; j < 4; j++) b[j] = Ws[kk][tx * 4 + j];
#pragma unroll
            for (int i = 0; i < 4; i++)
#pragma unroll
                for (int j = 0; j < 4; j++) acc[i][j] += a[i] * b[j];
        }
    }
    float* Pz = g_Phid + (size_t)z * (BB * DDH);
#pragma unroll
    for (int i = 0; i < 4; i++)
#pragma unroll
        for (int j = 0; j < 4; j++)
            Pz[(ty * 4 + i) * DDH + n0 + tx * 4 + j] = acc[i][j];
}

__global__ void k_init(const float* __restrict__ init_b) {
    int i = blockIdx.x * blockDim.x + threadIdx.x;    // < 64*1024
    int b = i >> 10, j = i & 1023;
    float c = init_b[j];
#pragma unroll
    for (int s = 0; s < 4; s++) c += g_Phid[s * (BB * DDH) + i];
    g_c[i] = c;
    float h = tanhf(c);
    g_h[i] = h;
    g_xb[b * 2048 + 1024 + j] = __float2bfloat16(h);
    g_xb[b * 2048 + j] = __float2bfloat16(0.f);       // av0 = 0
}

// ---------------- attention ----------------
__global__ void k_attn(const int* __restrict__ src_lens) {
    __shared__ float sh[1024];
    __shared__ float sc[64];
    __shared__ float sp[64];
    int b = blockIdx.x, tid = threadIdx.x;   // 256 threads
    *(float4*)(sh + tid * 4) = *(const float4*)(g_h + (size_t)b * DDH + tid * 4);
    __syncthreads();
    {
        int tt = tid >> 2, q = tid & 3;
        const bf162* He = (const bf162*)(g_Hencb + (size_t)(b * TSR + tt) * 1024 + q * 256);
        const float* hh = sh + q * 256;
        float s = 0.f;
#pragma unroll 8
        for (int j = 0; j < 128; j++) {
            bf162 v = He[j];
            s += hh[2 * j] * __bfloat162float(v.x) + hh[2 * j + 1] * __bfloat162float(v.y);
        }
        s += __shfl_xor_sync(0xffffffffu, s, 1);
        s += __shfl_xor_sync(0xffffffffu, s, 2);
        if (q == 0) sc[tt] = s;
    }
    __syncthreads();
    int L = src_lens[b];
    float m = -1e30f;
    for (int u = 0; u < 64; u++) if (u < L) m = fmaxf(m, sc[u]);
    float den = 0.f;
    for (int u = 0; u < 64; u++) if (u < L) den += __expf(sc[u] - m);
    if (tid < 64) sp[tid] = (tid < L) ? (__expf(sc[tid] - m) / den) : 0.f;
    __syncthreads();
    int j0 = tid * 4;
    float a0 = 0.f, a1 = 0.f, a2 = 0.f, a3 = 0.f;
    for (int u = 0; u < L; u++) {
        float p = sp[u];
        const bf162* Hr = (const bf162*)(g_Hencb + (size_t)(b * TSR + u) * 1024 + j0);
        bf162 v0 = Hr[0], v1 = Hr[1];
        a0 += p * __bfloat162float(v0.x); a1 += p * __bfloat162float(v0.y);
        a2 += p * __bfloat162float(v1.x); a3 += p * __bfloat162float(v1.y);
    }
    bf162* co = (bf162*)(g_yb + b * 2048 + 1024 + j0);
    co[0] = cvt2(a0, a1); co[1] = cvt2(a2, a3);
}

// ---------------- per-row LSE combine + masked sum ----------------
__global__ void k_rowlse() {
    int tid = threadIdx.x;                 // 256
    int b = tid >> 2, q = tid & 3;
    int row = blockIdx.x * 64 + b;
    const float* ch = g_chunk + (size_t)row * NTV * 2;
    float m = -1e30f;
    for (int i = q; i < NTV; i += 4) m = fmaxf(m, ch[2 * i]);
    m = fmaxf(m, __shfl_xor_sync(0xffffffffu, m, 1));
    m = fmaxf(m, __shfl_xor_sync(0xffffffffu, m, 2));
    float s = 0.f;
    for (int i = q; i < NTV; i += 4) s += ch[2 * i + 1] * __expf(ch[2 * i] - m);
    s += __shfl_xor_sync(0xffffffffu, s, 1);
    s += __shfl_xor_sync(0xffffffffu, s, 2);
    if (q == 0) {
        float lse = m + logf(s);
        g_rowval[row] = (g_gold[row] - lse) * g_maskf[row];
    }
}

__global__ void k_sum(float* __restrict__ out) {
    __shared__ float sm[256];
    int tid = threadIdx.x;
    float s = 0.f;
    for (int i = tid; i < MR; i += 256) s += g_rowval[i];
    sm[tid] = s;
    __syncthreads();
    for (int st = 128; st > 0; st >>= 1) {
        if (tid < st) sm[tid] += sm[tid + st];
        __syncthreads();
    }
    if (tid == 0) out[0] = sm[0];
}

// ---------------- launch ----------------
extern "C" void kernel_launch(void* const* d_in, const int* in_sizes, int n_in,
                              void* d_out, int out_size) {
    (void)in_sizes; (void)n_in; (void)out_size;
    const int*   src_tokens = (const int*)d_in[0];
    const int*   src_lens   = (const int*)d_in[1];
    const int*   trg_tokens = (const int*)d_in[2];
    const int*   trg_lens   = (const int*)d_in[3];
    const float* src_emb    = (const float*)d_in[4];
    const float* trg_emb    = (const float*)d_in[5];
    const float* enc_Wih    = (const float*)d_in[6];
    const float* enc_Whh    = (const float*)d_in[7];
    const float* enc_b      = (const float*)d_in[8];
    const float* rev_Wih    = (const float*)d_in[9];
    const float* rev_Whh    = (const float*)d_in[10];
    const float* rev_b      = (const float*)d_in[11];
    const float* dec_Wih    = (const float*)d_in[12];
    const float* dec_Whh    = (const float*)d_in[13];
    const float* dec_b      = (const float*)d_in[14];
    const float* hid_W      = (const float*)d_in[15];
    const float* hid_b      = (const float*)d_in[16];
    const float* out_W      = (const float*)d_in[17];
    const float* out_b      = (const float*)d_in[18];
    const float* init_W     = (const float*)d_in[19];
    const float* init_b     = (const float*)d_in[20];

    bf16 *p_svb, *p_tvb, *p_Wencf, *p_Wencr, *p_Whhf, *p_Whhr, *p_WdecE, *p_WhidB, *p_Wout;
    float *p_Gf, *p_Gr, *p_Gdec, *p_bencf, *p_bencr, *p_bdec;
    cudaGetSymbolAddress((void**)&p_svb, g_svb);
    cudaGetSymbolAddress((void**)&p_tvb, g_tvb);
    cudaGetSymbolAddress((void**)&p_Wencf, g_WencfP);
    cudaGetSymbolAddress((void**)&p_Wencr, g_WencrP);
    cudaGetSymbolAddress((void**)&p_Whhf, g_WhhfP);
    cudaGetSymbolAddress((void**)&p_Whhr, g_WhhrP);
    cudaGetSymbolAddress((void**)&p_WdecE, g_WdecE);
    cudaGetSymbolAddress((void**)&p_WhidB, g_WhidB);
    cudaGetSymbolAddress((void**)&p_Wout, g_Wout);
    cudaGetSymbolAddress((void**)&p_Gf, g_Gf);
    cudaGetSymbolAddress((void**)&p_Gr, g_Gr);
    cudaGetSymbolAddress((void**)&p_Gdec, g_Gdec);
    cudaGetSymbolAddress((void**)&p_bencf, g_bencfP);
    cudaGetSymbolAddress((void**)&p_bencr, g_bencrP);
    cudaGetSymbolAddress((void**)&p_bdec, g_bdecP);

    k_zero_state<<<256, 256>>>();
    k_gather_src<<<BB * TSR, 128>>>(src_tokens, src_emb);
    k_gather_trg<<<MR, 128>>>(trg_tokens, trg_lens, trg_emb);

    // weight conversions + gate-interleave permutations
    k_permW512<<<2048, 128>>>(enc_Wih, p_Wencf, 512, 512);
    k_permW512<<<2048, 128>>>(rev_Wih, p_Wencr, 512, 512);
    k_permW512<<<2048, 128>>>(enc_Whh, p_Whhf, 512, 512);
    k_permW512<<<2048, 128>>>(rev_Whh, p_Whhr, 512, 512);
    k_permW512<<<4096, 128>>>(dec_Wih, p_WdecE, 1024, 1536);
    k_permDecR<<<4096, 256>>>(dec_Wih, dec_Whh);
    k_permB<<<8, 256>>>(enc_b, p_bencf, 512);
    k_permB<<<8, 256>>>(rev_b, p_bencr, 512);
    k_permB<<<16, 256>>>(dec_b, p_bdec, 1024);
    k_f2b<<<(DDH * 2048 / 4 + 255) / 256, 256>>>(hid_W, p_WhidB, DDH * 2048 / 4);
    k_f2b<<<(VOC * DDH / 4 + 255) / 256, 256>>>(out_W, p_Wout, VOC * DDH / 4);

    // input projections (tensor cores, interleaved outputs)
    k_ff<<<dim3(64, 16), 256>>>(p_svb, EE, p_Wencf, EE, p_bencf, p_Gf, 2048, EE);
    k_ff<<<dim3(64, 16), 256>>>(p_svb, EE, p_Wencr, EE, p_bencr, p_Gr, 2048, EE);
    k_ff<<<dim3(63, 32), 256>>>(p_tvb, EE, p_WdecE, EE, p_bdec, p_Gdec, 4096, EE);

    // encoder recurrence: one fused kernel per step (both dirs)
    for (int t = 0; t < TSR; t++)
        k_enc_step<<<dim3(16, 2), 256>>>(t, p_Whhf, p_Whhr);

    // decoder init state
    k_final<<<512, 256>>>(src_lens);
    k_sgemm_init<<<dim3(32, 1, 4), 128>>>(init_W);
    k_init<<<256, 256>>>(init_b);

    // decoder recurrence: 3 kernels per step
    for (int t = 0; t < TD; t++) {
        k_dec_step<<<32, 256>>>(t);
        k_attn<<<BB, 256>>>(src_lens);
        k_hid<<<8, 256>>>(hid_b, t);
    }

    // vocab projection + LSE (tensor cores)
    k_vocab<<<dim3(63, NTV), 256>>>(out_b);
    k_rowlse<<<63, 256>>>();
    k_sum<<<1, 256>>>((float*)d_out);
}

// round 7
// speedup vs baseline: 3.1246x; 1.4943x over previous
#include <cuda_runtime.h>
#include <cuda_bf16.h>
#include <mma.h>
#include <math.h>
using namespace nvcuda;

// ---------------- problem constants ----------------
#define BB   64      // batch
#define TSR  64      // src len
#define TTR  64      // trg len
#define EE   512     // embedding
#define HH   512     // encoder hidden per dir
#define DDH  1024    // decoder hidden
#define VOC  32000
#define TD   63              // decode steps
#define MR   (TD*BB)         // 4032 rows of av
#define NTV  (VOC/128)       // 250 column tiles of vocab
#define NBE  32              // encoder persistent grid
#define NBD  128             // decoder persistent grid

typedef __nv_bfloat16 bf16;
typedef __nv_bfloat162 bf162;

// ---------------- static device scratch ----------------
__device__ bf16 g_svb  [BB*TSR*EE];       // src embedded bf16, row = b*TSR+t
__device__ bf16 g_tvb  [MR*EE];           // trg embedded bf16, row = t*BB+b
__device__ bf16 g_WencfP[4*HH*EE];        // enc_Wih bf16, gate-interleaved rows
__device__ bf16 g_WencrP[4*HH*EE];
__device__ bf16 g_WhhfP [4*HH*HH];        // enc_Whh bf16 interleaved
__device__ bf16 g_WhhrP [4*HH*HH];
__device__ bf16 g_WdecE [4*DDH*EE];       // dec_Wih[:, :512] interleaved
__device__ bf16 g_WdecR [4*DDH*2048];     // [dec_Wih[:,512:1536] | dec_Whh] interleaved
__device__ bf16 g_WhidB [DDH*2*DDH];      // hid_W bf16 plain
__device__ bf16 g_Wout  [VOC*DDH];        // out_W bf16 plain
__device__ bf16 g_avallb[MR*DDH];         // all av rows bf16

__device__ float g_bencfP[4*HH];          // permuted biases (fp32)
__device__ float g_bencrP[4*HH];
__device__ float g_bdecP [4*DDH];

__device__ float g_Gf   [BB*TSR*4*HH];    // enc fwd preact (interleaved cols)
__device__ float g_Gr   [BB*TSR*4*HH];
__device__ float g_Gdec [MR*4*DDH];       // dec preact (emb part + bias, interleaved)
__device__ float g_Henc [BB*TSR*2*HH];    // fp32 (for final-state gather)
__device__ float g_Cenc [BB*TSR*2*HH];
__device__ bf16  g_Hencb[BB*TSR*2*HH];    // bf16 copy for attention
__device__ bf16  g_hsb  [2*BB*HH];        // enc running h bf16 (both dirs)
__device__ float g_cs   [2*BB*HH];        // enc running c fp32
__device__ float g_c    [BB*DDH];         // dec c fp32
__device__ bf16  g_xb   [BB*2048];        // [av | h] bf16: gates GEMM input
__device__ bf16  g_yb   [BB*2048];        // [h | ctx] bf16: hid GEMM input
__device__ float g_Pg   [4*BB*4*DDH];     // gates split-K partials (4 x [64,4096])
__device__ float g_Ph   [4*BB*DDH];       // hid split-K partials (4 x [64,1024])
__device__ float g_Phid [4*BB*DDH];       // init-GEMM split-K partials
__device__ float g_final[BB*2*DDH];       // concat(Henc,Cenc) at last
__device__ float g_chunk[MR*NTV*2];       // per-tile (max, sumexp)
__device__ float g_gold [MR];
__device__ int   g_goldtok[MR];
__device__ float g_maskf[MR];
__device__ float g_rowval[MR];
__device__ unsigned g_bar[8];             // [0]=cntE [1]=genE [4]=cntD [5]=genD

__device__ __forceinline__ float sigf(float x) { return 1.0f / (1.0f + expf(-x)); }
__device__ __forceinline__ bf162 cvt2(float a, float b) {
    return __float22bfloat162_rn(make_float2(a, b));
}

// ---------------- device-wide software barrier ----------------
// All blocks of the (co-resident) grid must call with the same base.
__device__ __forceinline__ void gsync(int base, unsigned nb, unsigned& mygen) {
    __threadfence();
    __syncthreads();
    if (threadIdx.x == 0) {
        unsigned g = mygen;
        if (atomicAdd(&g_bar[base], 1u) == nb - 1u) {
            atomicExch(&g_bar[base], 0u);
            __threadfence();
            atomicExch(&g_bar[base + 1], g + 1u);
        } else {
            volatile unsigned* vg = (volatile unsigned*)&g_bar[base + 1];
            while (*vg == g) __nanosleep(64);
        }
    }
    mygen++;
    __syncthreads();
}

// ============ shared 64x128 GEMM core (bf16, fp32 accum) ============
// 256 threads / 8 warps. Double-buffered smem, one sync per K-iter.
// Result left in Cs[64][136] (smem, aliased with the staging buffers).
__device__ __forceinline__ void gemm_core(
    const bf16* __restrict__ A, int lda,
    const bf16* __restrict__ W, int ldw,   // W tile base: 128 rows
    int K, float* Cs)
{
    bf16* As = (bf16*)Cs;            // 2 * 64 * 40 bf16
    bf16* Ws = (bf16*)Cs + 5120;     // 2 * 128 * 40 bf16
    int tid = threadIdx.x;
    int wid = tid >> 5;
    int wr = (wid & 1) * 32, wc = (wid >> 1) * 32;

    wmma::fragment<wmma::accumulator, 16, 16, 16, float> acc[2][2];
#pragma unroll
    for (int i = 0; i < 2; i++)
#pragma unroll
        for (int j = 0; j < 2; j++) wmma::fill_fragment(acc[i][j], 0.f);

    int lr = tid >> 2, lc = (tid & 3) * 8;
    const bf16* Ap  = A + (size_t)lr * lda + lc;
    const bf16* Wp0 = W + (size_t)lr * ldw + lc;
    const bf16* Wp1 = W + (size_t)(lr + 64) * ldw + lc;

    float4 ra  = *(const float4*)Ap;
    float4 rw0 = *(const float4*)Wp0;
    float4 rw1 = *(const float4*)Wp1;
    *(float4*)&As[lr * 40 + lc] = ra;
    *(float4*)&Ws[lr * 40 + lc] = rw0;
    *(float4*)&Ws[(lr + 64) * 40 + lc] = rw1;

    int niter = K >> 5;
    int cur = 0;
    for (int it = 0; it < niter; ++it) {
        __syncthreads();
        if (it + 1 < niter) {
            ra  = *(const float4*)(Ap  + (it + 1) * 32);
            rw0 = *(const float4*)(Wp0 + (it + 1) * 32);
            rw1 = *(const float4*)(Wp1 + (it + 1) * 32);
        }
        const bf16* Ab = As + cur * (64 * 40);
        const bf16* Wb = Ws + cur * (128 * 40);
#pragma unroll
        for (int kk = 0; kk < 32; kk += 16) {
            wmma::fragment<wmma::matrix_a, 16, 16, 16, bf16, wmma::row_major> af[2];
            wmma::fragment<wmma::matrix_b, 16, 16, 16, bf16, wmma::col_major> bfr[2];
            wmma::load_matrix_sync(af[0], Ab + wr * 40 + kk, 40);
            wmma::load_matrix_sync(af[1], Ab + (wr + 16) * 40 + kk, 40);
            wmma::load_matrix_sync(bfr[0], Wb + wc * 40 + kk, 40);
            wmma::load_matrix_sync(bfr[1], Wb + (wc + 16) * 40 + kk, 40);
#pragma unroll
            for (int i = 0; i < 2; i++)
#pragma unroll
                for (int j = 0; j < 2; j++)
                    wmma::mma_sync(acc[i][j], af[i], bfr[j], acc[i][j]);
        }
        if (it + 1 < niter) {
            int nb = cur ^ 1;
            *(float4*)&As[(nb * 64 + lr) * 40 + lc] = ra;
            *(float4*)&Ws[(nb * 128 + lr) * 40 + lc] = rw0;
            *(float4*)&Ws[(nb * 128 + lr + 64) * 40 + lc] = rw1;
        }
        cur ^= 1;
    }
    __syncthreads();
#pragma unroll
    for (int i = 0; i < 2; i++)
#pragma unroll
        for (int j = 0; j < 2; j++)
            wmma::store_matrix_sync(Cs + (wr + i * 16) * 136 + wc + j * 16,
                                    acc[i][j], 136, wmma::mem_row_major);
    __syncthreads();
}

// ---------------- conversions / permutations ----------------
__global__ void k_f2b(const float* __restrict__ x, bf16* __restrict__ y, int n4) {
    int i = blockIdx.x * blockDim.x + threadIdx.x;
    if (i < n4) {
        float4 v = ((const float4*)x)[i];
        ((bf162*)y)[2 * i]     = cvt2(v.x, v.y);
        ((bf162*)y)[2 * i + 1] = cvt2(v.z, v.w);
    }
}

// out row (4j+g) <- W row (g*J+j), first 512 cols of ldin
__global__ void k_permW512(const float* __restrict__ W, bf16* __restrict__ out,
                           int J, int ldin) {
    int row = blockIdx.x;
    int j = row >> 2, g = row & 3;
    const float4* src = (const float4*)(W + (size_t)(g * J + j) * ldin);
    bf162* dst = (bf162*)(out + (size_t)row * 512);
    int t = threadIdx.x;                   // 128
    float4 v = src[t];
    dst[2 * t]     = cvt2(v.x, v.y);
    dst[2 * t + 1] = cvt2(v.z, v.w);
}

__global__ void k_permDecR(const float* __restrict__ Wih, const float* __restrict__ Whh) {
    int row = blockIdx.x;                  // 4096
    int j = row >> 2, g = row & 3;
    int t = threadIdx.x;                   // 256, 8 elems each
    const float* src = (t < 128)
        ? (Wih + (size_t)(g * 1024 + j) * 1536 + 512 + t * 8)
        : (Whh + (size_t)(g * 1024 + j) * 1024 + (t - 128) * 8);
    bf162* dst = (bf162*)(g_WdecR + (size_t)row * 2048 + t * 8);
    float4 a = *(const float4*)src;
    float4 b = *(const float4*)(src + 4);
    dst[0] = cvt2(a.x, a.y); dst[1] = cvt2(a.z, a.w);
    dst[2] = cvt2(b.x, b.y); dst[3] = cvt2(b.z, b.w);
}

__global__ void k_permB(const float* __restrict__ b, float* __restrict__ out, int J) {
    int i = blockIdx.x * blockDim.x + threadIdx.x;
    if (i < 4 * J) { int j = i >> 2, g = i & 3; out[i] = b[g * J + j]; }
}

// ---------------- init / gathers ----------------
__global__ void k_zero_state() {
    int i = blockIdx.x * blockDim.x + threadIdx.x;
    if (i < 2 * BB * HH) { g_cs[i] = 0.f; g_hsb[i] = __float2bfloat16(0.f); }
    if (i < 8) g_bar[i] = 0u;
}

__global__ void k_gather_src(const int* __restrict__ tok, const float* __restrict__ emb) {
    int r = blockIdx.x;
    int v = tok[r];
    float4 val = ((const float4*)(emb + (size_t)v * EE))[threadIdx.x];
    bf162* d = (bf162*)(g_svb + (size_t)r * EE + threadIdx.x * 4);
    d[0] = cvt2(val.x, val.y); d[1] = cvt2(val.z, val.w);
}

__global__ void k_gather_trg(const int* __restrict__ tok, const int* __restrict__ lens,
                             const float* __restrict__ emb) {
    int r = blockIdx.x;                    // t*BB + b
    int t = r >> 6, b = r & 63;
    int v = tok[b * TTR + t];
    float4 val = ((const float4*)(emb + (size_t)v * EE))[threadIdx.x];
    bf162* d = (bf162*)(g_tvb + (size_t)r * EE + threadIdx.x * 4);
    d[0] = cvt2(val.x, val.y); d[1] = cvt2(val.z, val.w);
    if (threadIdx.x == 0) {
        g_goldtok[r] = tok[b * TTR + t + 1];
        g_maskf[r] = ((t + 1) < lens[b]) ? 1.0f : 0.0f;
    }
}

// ---------------- feed-forward GEMM: C = A @ W^T + bias ----------------
__global__ __launch_bounds__(256) void k_ff(
    const bf16* __restrict__ A, int lda,
    const bf16* __restrict__ W, int ldw,
    const float* __restrict__ bias,
    float* __restrict__ C, int ldc, int K)
{
    __shared__ __align__(16) float Cs[64 * 136];
    int m0 = blockIdx.x * 64, n0 = blockIdx.y * 128;
    gemm_core(A + (size_t)m0 * lda, lda, W + (size_t)n0 * ldw, ldw, K, Cs);
    int tid = threadIdx.x;
    for (int e = tid; e < 2048; e += 256) {
        int r = e >> 5, c4 = (e & 31) * 4;
        float4 v = *(const float4*)(Cs + r * 136 + c4);
        float4 bv = *(const float4*)(bias + n0 + c4);
        v.x += bv.x; v.y += bv.y; v.z += bv.z; v.w += bv.w;
        *(float4*)(C + (size_t)(m0 + r) * ldc + n0 + c4) = v;
    }
}

// ---------------- vocab GEMM + fused LSE chunk ----------------
__global__ __launch_bounds__(256) void k_vocab(const float* __restrict__ bias) {
    __shared__ __align__(16) float Cs[64 * 136];
    int m0 = blockIdx.x * 64, n0 = blockIdx.y * 128;
    gemm_core(g_avallb + (size_t)m0 * DDH, DDH, g_Wout + (size_t)n0 * DDH, DDH, DDH, Cs);
    int tid = threadIdx.x;
    for (int e = tid; e < 2048; e += 256) {
        int r = e >> 5, c4 = (e & 31) * 4;
        float4 v = *(const float4*)(Cs + r * 136 + c4);
        float4 bv = *(const float4*)(bias + n0 + c4);
        v.x += bv.x; v.y += bv.y; v.z += bv.z; v.w += bv.w;
        *(float4*)(Cs + r * 136 + c4) = v;
    }
    __syncthreads();
    int row = tid >> 2, q = tid & 3;
    const float* Cr = Cs + row * 136 + q * 32;
    float m = -1e30f;
#pragma unroll 8
    for (int c = 0; c < 32; c++) m = fmaxf(m, Cr[c]);
    m = fmaxf(m, __shfl_xor_sync(0xffffffffu, m, 1));
    m = fmaxf(m, __shfl_xor_sync(0xffffffffu, m, 2));
    float s = 0.f;
#pragma unroll 8
    for (int c = 0; c < 32; c++) s += __expf(Cr[c] - m);
    s += __shfl_xor_sync(0xffffffffu, s, 1);
    s += __shfl_xor_sync(0xffffffffu, s, 2);
    int rg = m0 + row;
    if (q == 0) {
        size_t co = ((size_t)rg * NTV + blockIdx.y) * 2;
        g_chunk[co + 0] = m;
        g_chunk[co + 1] = s;
    }
    int loc = g_goldtok[rg] - n0;
    if (loc >= q * 32 && loc < q * 32 + 32) g_gold[rg] = Cs[row * 136 + loc];
}

// ---------------- persistent encoder: 64 steps, fused gates GEMM + cell ----------------
__global__ __launch_bounds__(256) void k_enc_persist(
    const bf16* __restrict__ Wf, const bf16* __restrict__ Wr)
{
    __shared__ __align__(16) float Cs[64 * 136];
    unsigned gen = 0;
    int p = blockIdx.x, tid = threadIdx.x;
    int d = p >> 4;
    int n0 = (p & 15) * 128;               // of 2048 interleaved cols
    const bf16* A = g_hsb + d * (BB * HH);
    const bf16* W = (d ? Wr : Wf) + (size_t)n0 * HH;
    const float* pre_base = d ? g_Gr : g_Gf;
    for (int t = 0; t < TSR; t++) {
        gemm_core(A, HH, W, HH, HH, Cs);
        for (int it = tid; it < 2048; it += 256) {
            int b = it >> 5, jl = it & 31;
            const float* cr = Cs + b * 136 + 4 * jl;
            const float* pre = pre_base + (size_t)(b * TSR + t) * 2048 + n0 + 4 * jl;
            float gi = cr[0] + pre[0];
            float gf = cr[1] + pre[1];
            float gg = cr[2] + pre[2];
            float go = cr[3] + pre[3];
            int j = (n0 >> 2) + jl;
            int si = d * (BB * HH) + (b << 9) + j;
            float c = sigf(gf) * g_cs[si] + sigf(gi) * tanhf(gg);
            float h = sigf(go) * tanhf(c);
            g_cs[si] = c;
            g_hsb[si] = __float2bfloat16(h);
            size_t o = (size_t)(b * TSR + t) * 1024 + d * 512 + j;
            g_Henc[o] = h; g_Cenc[o] = c; g_Hencb[o] = __float2bfloat16(h);
        }
        gsync(0, NBE, gen);
    }
}

// ---------------- persistent decoder: 63 steps ----------------
__global__ __launch_bounds__(256) void k_dec_persist(
    const int* __restrict__ src_lens, const float* __restrict__ hid_b)
{
    __shared__ __align__(16) float Cs[64 * 136];
    unsigned gen = 0;
    int p = blockIdx.x, tid = threadIdx.x;
    for (int t = 0; t < TD; t++) {
        // ---- Phase A: gates partial GEMM (all 128 blocks) ----
        {
            int nt = p & 31, ks = p >> 5;
            gemm_core(g_xb + ks * 512, 2048,
                      g_WdecR + (size_t)(nt * 128) * 2048 + ks * 512, 2048, 512, Cs);
            float* Pz = g_Pg + (size_t)ks * (64 * 4096);
            for (int e = tid; e < 64 * 128; e += 256) {
                int r = e >> 7, c = e & 127;
                Pz[r * 4096 + nt * 128 + c] = Cs[r * 136 + c];
            }
        }
        gsync(4, NBD, gen);
        // ---- Phase B: cell + attention, block b = p (p < 64) ----
        if (p < 64) {
            int b = p;
            float* sh = Cs;            // 1024
            float* sc = Cs + 1024;     // 64
            float* sp = Cs + 1088;     // 64
#pragma unroll
            for (int u = 0; u < 4; u++) {
                int j = tid + u * 256;
                int col = 4 * j;
                const float* pre = g_Gdec + (size_t)((t << 6) + b) * 4096;
                float gi = pre[col], gf = pre[col + 1], gg = pre[col + 2], go = pre[col + 3];
#pragma unroll
                for (int s = 0; s < 4; s++) {
                    const float* Ps = g_Pg + (size_t)s * (64 * 4096) + (size_t)b * 4096;
                    gi += Ps[col]; gf += Ps[col + 1]; gg += Ps[col + 2]; go += Ps[col + 3];
                }
                int ci = (b << 10) + j;
                float c = sigf(gf) * g_c[ci] + sigf(gi) * tanhf(gg);
                float h = sigf(go) * tanhf(c);
                g_c[ci] = c;
                sh[j] = h;
                bf16 hb = __float2bfloat16(h);
                g_xb[b * 2048 + 1024 + j] = hb;     // next step's gates input
                g_yb[b * 2048 + j] = hb;            // hid GEMM input
            }
            __syncthreads();
            // attention scores
            {
                int tt = tid >> 2, q = tid & 3;
                const bf162* He = (const bf162*)(g_Hencb + (size_t)(b * TSR + tt) * 1024 + q * 256);
                const float* hh = sh + q * 256;
                float s = 0.f;
#pragma unroll 8
                for (int j = 0; j < 128; j++) {
                    bf162 v = He[j];
                    s += hh[2 * j] * __bfloat162float(v.x) + hh[2 * j + 1] * __bfloat162float(v.y);
                }
                s += __shfl_xor_sync(0xffffffffu, s, 1);
                s += __shfl_xor_sync(0xffffffffu, s, 2);
                if (q == 0) sc[tt] = s;
            }
            __syncthreads();
            int L = src_lens[b];
            float m = -1e30f;
            for (int u = 0; u < 64; u++) if (u < L) m = fmaxf(m, sc[u]);
            float den = 0.f;
            for (int u = 0; u < 64; u++) if (u < L) den += __expf(sc[u] - m);
            if (tid < 64) sp[tid] = (tid < L) ? (__expf(sc[tid] - m) / den) : 0.f;
            __syncthreads();
            int j0 = tid * 4;
            float a0 = 0.f, a1 = 0.f, a2 = 0.f, a3 = 0.f;
            for (int u = 0; u < L; u++) {
                float pw = sp[u];
                const bf162* Hr = (const bf162*)(g_Hencb + (size_t)(b * TSR + u) * 1024 + j0);
                bf162 v0 = Hr[0], v1 = Hr[1];
                a0 += pw * __bfloat162float(v0.x); a1 += pw * __bfloat162float(v0.y);
                a2 += pw * __bfloat162float(v1.x); a3 += pw * __bfloat162float(v1.y);
            }
            bf162* co = (bf162*)(g_yb + b * 2048 + 1024 + j0);
            co[0] = cvt2(a0, a1); co[1] = cvt2(a2, a3);
        }
        gsync(4, NBD, gen);
        // ---- Phase C: hid partial GEMM (p < 32) ----
        if (p < 32) {
            int nt = p & 7, ks = p >> 3;
            gemm_core(g_yb + ks * 512, 2048,
                      g_WhidB + (size_t)(nt * 128) * 2048 + ks * 512, 2048, 512, Cs);
            float* Pz = g_Ph + (size_t)ks * (64 * 1024);
            for (int e = tid; e < 64 * 128; e += 256) {
                int r = e >> 7, c = e & 127;
                Pz[r * 1024 + nt * 128 + c] = Cs[r * 136 + c];
            }
        }
        gsync(4, NBD, gen);
        // ---- Phase D: av combine (all blocks, 512 elems each) ----
        for (int i = tid; i < 512; i += 256) {
            int idx = p * 512 + i;
            int b = idx >> 10, j = idx & 1023;
            float v = hid_b[j];
#pragma unroll
            for (int s = 0; s < 4; s++) v += g_Ph[s * (64 * 1024) + idx];
            bf16 vb = __float2bfloat16(v);
            g_xb[b * 2048 + j] = vb;                           // av for next gates GEMM
            g_avallb[(size_t)((t << 6) + b) * 1024 + j] = vb;  // vocab GEMM row
        }
        gsync(4, NBD, gen);
    }
}

// ---------------- decoder init (fp32 path, one-time) ----------------
__global__ void k_final(const int* __restrict__ src_lens) {
    int i = blockIdx.x * blockDim.x + threadIdx.x;    // < 64*2048
    int b = i >> 11, j = i & 2047;
    int last = src_lens[b] - 1;
    size_t o = (size_t)(b * TSR + last) * 1024;
    g_final[i] = (j < 1024) ? g_Henc[o + j] : g_Cenc[o + j - 1024];
}

__global__ void k_sgemm_init(const float* __restrict__ W) {
    __shared__ float As[16][64];
    __shared__ float Ws[16][32];
    int z = blockIdx.z;
    int koff = z * 512;
    int tid = threadIdx.x;
    int n0 = blockIdx.x * 32;
    int ty = tid >> 3, tx = tid & 7;
    int lr = tid >> 1, lc = (tid & 1) * 8;
    int wr = tid >> 2, wc = (tid & 3) * 4;
    float acc[4][4];
#pragma unroll
    for (int i = 0; i < 4; i++)
#pragma unroll
        for (int j = 0; j < 4; j++) acc[i][j] = 0.f;
    const float* Ab = g_final + (size_t)lr * 2048 + koff + lc;
    const float* Wb = W + (size_t)(n0 + wr) * 2048 + koff + wc;
    for (int k0 = 0; k0 < 512; k0 += 16) {
        float4 a0 = *(const float4*)(Ab + k0);
        float4 a1 = *(const float4*)(Ab + k0 + 4);
        float4 b0 = *(const float4*)(Wb + k0);
        __syncthreads();
        As[lc + 0][lr] = a0.x; As[lc + 1][lr] = a0.y; As[lc + 2][lr] = a0.z; As[lc + 3][lr] = a0.w;
        As[lc + 4][lr] = a1.x; As[lc + 5][lr] = a1.y; As[lc + 6][lr] = a1.z; As[lc + 7][lr] = a1.w;
        Ws[wc + 0][wr] = b0.x; Ws[wc + 1][wr] = b0.y; Ws[wc + 2][wr] = b0.z; Ws[wc + 3][wr] = b0.w;
        __syncthreads();
#pragma unroll
        for (int kk = 0; kk < 16; kk++) {
            float a[4], b[4];
#pragma unroll
            for (int i = 0; i < 4; i++) a[i] = As[kk][ty * 4 + i];
#pragma unroll
            for (int j = 0; j < 4; j++) b[j] = Ws[kk][tx * 4 + j];
#pragma unroll
            for (int i = 0; i < 4; i++)
#pragma unroll
                for (int j = 0; j < 4; j++) acc[i][j] += a[i] * b[j];
        }
    }
    float* Pz = g_Phid + (size_t)z * (BB * DDH);
#pragma unroll
    for (int i = 0; i < 4; i++)
#pragma unroll
        for (int j = 0; j < 4; j++)
            Pz[(ty * 4 + i) * DDH + n0 + tx * 4 + j] = acc[i][j];
}

__global__ void k_init(const float* __restrict__ init_b) {
    int i = blockIdx.x * blockDim.x + threadIdx.x;    // < 64*1024
    int b = i >> 10, j = i & 1023;
    float c = init_b[j];
#pragma unroll
    for (int s = 0; s < 4; s++) c += g_Phid[s * (BB * DDH) + i];
    g_c[i] = c;
    float h = tanhf(c);
    g_xb[b * 2048 + 1024 + j] = __float2bfloat16(h);
    g_xb[b * 2048 + j] = __float2bfloat16(0.f);       // av0 = 0
}

// ---------------- per-row LSE combine + masked sum ----------------
__global__ void k_rowlse() {
    int tid = threadIdx.x;                 // 256
    int b = tid >> 2, q = tid & 3;
    int row = blockIdx.x * 64 + b;
    const float* ch = g_chunk + (size_t)row * NTV * 2;
    float m = -1e30f;
    for (int i = q; i < NTV; i += 4) m = fmaxf(m, ch[2 * i]);
    m = fmaxf(m, __shfl_xor_sync(0xffffffffu, m, 1));
    m = fmaxf(m, __shfl_xor_sync(0xffffffffu, m, 2));
    float s = 0.f;
    for (int i = q; i < NTV; i += 4) s += ch[2 * i + 1] * __expf(ch[2 * i] - m);
    s += __shfl_xor_sync(0xffffffffu, s, 1);
    s += __shfl_xor_sync(0xffffffffu, s, 2);
    if (q == 0) {
        float lse = m + logf(s);
        g_rowval[row] = (g_gold[row] - lse) * g_maskf[row];
    }
}

__global__ void k_sum(float* __restrict__ out) {
    __shared__ float sm[256];
    int tid = threadIdx.x;
    float s = 0.f;
    for (int i = tid; i < MR; i += 256) s += g_rowval[i];
    sm[tid] = s;
    __syncthreads();
    for (int st = 128; st > 0; st >>= 1) {
        if (tid < st) sm[tid] += sm[tid + st];
        __syncthreads();
    }
    if (tid == 0) out[0] = sm[0];
}

// ---------------- launch ----------------
extern "C" void kernel_launch(void* const* d_in, const int* in_sizes, int n_in,
                              void* d_out, int out_size) {
    (void)in_sizes; (void)n_in; (void)out_size;
    const int*   src_tokens = (const int*)d_in[0];
    const int*   src_lens   = (const int*)d_in[1];
    const int*   trg_tokens = (const int*)d_in[2];
    const int*   trg_lens   = (const int*)d_in[3];
    const float* src_emb    = (const float*)d_in[4];
    const float* trg_emb    = (const float*)d_in[5];
    const float* enc_Wih    = (const float*)d_in[6];
    const float* enc_Whh    = (const float*)d_in[7];
    const float* enc_b      = (const float*)d_in[8];
    const float* rev_Wih    = (const float*)d_in[9];
    const float* rev_Whh    = (const float*)d_in[10];
    const float* rev_b      = (const float*)d_in[11];
    const float* dec_Wih    = (const float*)d_in[12];
    const float* dec_Whh    = (const float*)d_in[13];
    const float* dec_b      = (const float*)d_in[14];
    const float* hid_W      = (const float*)d_in[15];
    const float* hid_b      = (const float*)d_in[16];
    const float* out_W      = (const float*)d_in[17];
    const float* out_b      = (const float*)d_in[18];
    const float* init_W     = (const float*)d_in[19];
    const float* init_b     = (const float*)d_in[20];

    bf16 *p_svb, *p_tvb, *p_Wencf, *p_Wencr, *p_Whhf, *p_Whhr, *p_WdecE, *p_WhidB, *p_Wout;
    float *p_Gf, *p_Gr, *p_Gdec, *p_bencf, *p_bencr, *p_bdec;
    cudaGetSymbolAddress((void**)&p_svb, g_svb);
    cudaGetSymbolAddress((void**)&p_tvb, g_tvb);
    cudaGetSymbolAddress((void**)&p_Wencf, g_WencfP);
    cudaGetSymbolAddress((void**)&p_Wencr, g_WencrP);
    cudaGetSymbolAddress((void**)&p_Whhf, g_WhhfP);
    cudaGetSymbolAddress((void**)&p_Whhr, g_WhhrP);
    cudaGetSymbolAddress((void**)&p_WdecE, g_WdecE);
    cudaGetSymbolAddress((void**)&p_WhidB, g_WhidB);
    cudaGetSymbolAddress((void**)&p_Wout, g_Wout);
    cudaGetSymbolAddress((void**)&p_Gf, g_Gf);
    cudaGetSymbolAddress((void**)&p_Gr, g_Gr);
    cudaGetSymbolAddress((void**)&p_Gdec, g_Gdec);
    cudaGetSymbolAddress((void**)&p_bencf, g_bencfP);
    cudaGetSymbolAddress((void**)&p_bencr, g_bencrP);
    cudaGetSymbolAddress((void**)&p_bdec, g_bdecP);

    k_zero_state<<<256, 256>>>();
    k_gather_src<<<BB * TSR, 128>>>(src_tokens, src_emb);
    k_gather_trg<<<MR, 128>>>(trg_tokens, trg_lens, trg_emb);

    // weight conversions + gate-interleave permutations
    k_permW512<<<2048, 128>>>(enc_Wih, p_Wencf, 512, 512);
    k_permW512<<<2048, 128>>>(rev_Wih, p_Wencr, 512, 512);
    k_permW512<<<2048, 128>>>(enc_Whh, p_Whhf, 512, 512);
    k_permW512<<<2048, 128>>>(rev_Whh, p_Whhr, 512, 512);
    k_permW512<<<4096, 128>>>(dec_Wih, p_WdecE, 1024, 1536);
    k_permDecR<<<4096, 256>>>(dec_Wih, dec_Whh);
    k_permB<<<8, 256>>>(enc_b, p_bencf, 512);
    k_permB<<<8, 256>>>(rev_b, p_bencr, 512);
    k_permB<<<16, 256>>>(dec_b, p_bdec, 1024);
    k_f2b<<<(DDH * 2048 / 4 + 255) / 256, 256>>>(hid_W, p_WhidB, DDH * 2048 / 4);
    k_f2b<<<(VOC * DDH / 4 + 255) / 256, 256>>>(out_W, p_Wout, VOC * DDH / 4);

    // input projections (tensor cores, interleaved outputs)
    k_ff<<<dim3(64, 16), 256>>>(p_svb, EE, p_Wencf, EE, p_bencf, p_Gf, 2048, EE);
    k_ff<<<dim3(64, 16), 256>>>(p_svb, EE, p_Wencr, EE, p_bencr, p_Gr, 2048, EE);
    k_ff<<<dim3(63, 32), 256>>>(p_tvb, EE, p_WdecE, EE, p_bdec, p_Gdec, 4096, EE);

    // encoder recurrence: ONE persistent kernel (64 steps, grid-sync per step)
    k_enc_persist<<<NBE, 256>>>(p_Whhf, p_Whhr);

    // decoder init state
    k_final<<<512, 256>>>(src_lens);
    k_sgemm_init<<<dim3(32, 1, 4), 128>>>(init_W);
    k_init<<<256, 256>>>(init_b);

    // decoder recurrence: ONE persistent kernel (63 steps, 4 grid-syncs per step)
    k_dec_persist<<<NBD, 256>>>(src_lens, hid_b);

    // vocab projection + LSE (tensor cores)
    k_vocab<<<dim3(63, NTV), 256>>>(out_b);
    k_rowlse<<<63, 256>>>();
    k_sum<<<1, 256>>>((float*)d_out);
}